// round 15
// baseline (speedup 1.0000x reference)
#include <cuda_runtime.h>
#include <cuda_bf16.h>
#include <cuda_fp16.h>
#include <math.h>
#include <stdint.h>

// Problem constants
#define BBATCH 32
#define SFULL  201
#define SL     200
#define HDIM   512
#define EDIM   512
#define VDIM   32000
#define TDIM   101
#define MROWS  (BBATCH * SL)   // 6400
#define HT3    1536            // head|tail|gate fused width

// ---------------- scratch (device globals; no allocation allowed) ----------------
__device__ float g_hidden[MROWS * HDIM];
__device__ float g_hd3   [MROWS * HT3];     // [head | tail | gbuf] fused
__device__ float g_m1    [MROWS * HDIM];
__device__ float g_depend[MROWS * HDIM];
__device__ float g_ti    [128 * HDIM];      // elu(tl@wti+bti), 101 rows (pad 128)
__device__ float g_bias3 [HT3];
__device__ float g_rowmask[MROWS];
__device__ float g_pool  [MROWS];
__device__ int   g_gidx  [MROWS];
__device__ int   g_tidx  [MROWS];

// split-bf16 operand buffers (H-dim stages)
__device__ __nv_bfloat16 g_casHi[MROWS * HDIM];
__device__ __nv_bfloat16 g_casLo[MROWS * HDIM];
__device__ __nv_bfloat16 g_tlHi[128 * HDIM];
__device__ __nv_bfloat16 g_tlLo[128 * HDIM];
__device__ __nv_bfloat16 g_hidHi[MROWS * HDIM];
__device__ __nv_bfloat16 g_hidLo[MROWS * HDIM];
__device__ __nv_bfloat16 g_depHi[MROWS * HDIM];
__device__ __nv_bfloat16 g_depLo[MROWS * HDIM];
__device__ __nv_bfloat16 g_encHi[MROWS * HDIM];
__device__ __nv_bfloat16 g_encLo[MROWS * HDIM];
// 7 transposed/split weights [512,512]: w1(0), wh(1), wt(2), wg1(3), wg2(4), wm1(5), wti(6)
#define WSLOT (HDIM * HDIM)
__device__ __nv_bfloat16 g_wTHi[7 * WSLOT];
__device__ __nv_bfloat16 g_wTLo[7 * WSLOT];

// split-fp16 enc for the wout GEMM (pool folded into wout epilogue)
__device__ __half g_Af16hi[MROWS * HDIM];
__device__ __half g_Af16lo[MROWS * HDIM];
__device__ __half g_Bf16[(size_t)VDIM * HDIM];

// ---------------- base-PTX helpers (target is plain sm_103: no tcgen05!) --------
__device__ __forceinline__ uint32_t smem_u32(const void* p) {
    uint32_t a;
    asm("{ .reg .u64 t; cvta.to.shared.u64 t, %1; cvt.u32.u64 %0, t; }" : "=r"(a) : "l"(p));
    return a;
}

#define CP_ASYNC16(dst, src) \
    asm volatile("cp.async.cg.shared.global [%0], [%1], 16;" :: "r"(dst), "l"(src))
#define CP_COMMIT() asm volatile("cp.async.commit_group;" ::: "memory")
#define CP_WAIT1()  asm volatile("cp.async.wait_group 1;" ::: "memory")

#define LDSM4(r, addr)                                                        \
    asm volatile("ldmatrix.sync.aligned.m8n8.x4.shared.b16 {%0,%1,%2,%3}, [%4];" \
                 : "=r"((r)[0]), "=r"((r)[1]), "=r"((r)[2]), "=r"((r)[3])     \
                 : "r"(addr))

#define MMA_BF16(d, a, b0, b1)                                                \
    asm volatile("mma.sync.aligned.m16n8k16.row.col.f32.bf16.bf16.f32 "       \
                 "{%0,%1,%2,%3}, {%4,%5,%6,%7}, {%8,%9}, {%0,%1,%2,%3};"      \
                 : "+f"((d)[0]), "+f"((d)[1]), "+f"((d)[2]), "+f"((d)[3])     \
                 : "r"((a)[0]), "r"((a)[1]), "r"((a)[2]), "r"((a)[3]),        \
                   "r"(b0), "r"(b1))

#define MMA_F16(d, a, b0, b1)                                                 \
    asm volatile("mma.sync.aligned.m16n8k16.row.col.f32.f16.f16.f32 "         \
                 "{%0,%1,%2,%3}, {%4,%5,%6,%7}, {%8,%9}, {%0,%1,%2,%3};"      \
                 : "+f"((d)[0]), "+f"((d)[1]), "+f"((d)[2]), "+f"((d)[3])     \
                 : "r"((a)[0]), "r"((a)[1]), "r"((a)[2]), "r"((a)[3]),        \
                   "r"(b0), "r"(b1))

__device__ __forceinline__ float elu_f(float x) { return x > 0.0f ? x : expm1f(x); }

// ---------------- prep ----------------
__global__ void prep_kernel(const int* __restrict__ cas, const int* __restrict__ tii) {
    int b = blockIdx.x;
    int tid = threadIdx.x;
    __shared__ int red[256];
    int cnt = 0;
    for (int i = tid; i < SL; i += 256) cnt += (cas[b * SFULL + i] != 0);
    red[tid] = cnt;
    __syncthreads();
    for (int s = 128; s > 0; s >>= 1) {
        if (tid < s) red[tid] += red[tid + s];
        __syncthreads();
    }
    int len = red[0];
    for (int i = tid; i < SL; i += 256) {
        int r = b * SL + i;
        g_rowmask[r] = (i < len) ? 1.0f : 0.0f;
        g_gidx[r] = cas[b * SFULL + i];
        g_tidx[r] = tii[b * SFULL + i];
    }
}

__global__ void bias3_kernel(const float* __restrict__ bh, const float* __restrict__ bt,
                             const float* __restrict__ bg) {
    const int i = blockIdx.x * 256 + threadIdx.x;
    if (i >= HT3) return;
    g_bias3[i] = (i < 512) ? bh[i] : (i < 1024) ? bt[i - 512] : bg[i - 1024];
}

// ---------------- gather + split embedding rows ----------------
__global__ void gatherSplit_kernel(const float* __restrict__ emb) {
    const int idx = blockIdx.x * 256 + threadIdx.x;
    const int row = idx >> 9;
    const int col = idx & 511;
    const float x = emb[(size_t)g_gidx[row] * EDIM + col];
    const __nv_bfloat16 h = __float2bfloat16(x);
    g_casHi[idx] = h;
    g_casLo[idx] = __float2bfloat16(x - __bfloat162float(h));
}

__global__ void split_kernel(const float* __restrict__ src, __nv_bfloat16* __restrict__ hi,
                             __nv_bfloat16* __restrict__ lo, int n) {
    const int idx = blockIdx.x * 256 + threadIdx.x;
    if (idx >= n) return;
    const float x = src[idx];
    const __nv_bfloat16 h = __float2bfloat16(x);
    hi[idx] = h;
    lo[idx] = __float2bfloat16(x - __bfloat162float(h));
}

// ---------------- transpose + split (bf16) ----------------
__global__ void convT_kernel(const float* __restrict__ w, int ncols,
                             __nv_bfloat16* __restrict__ hi, __nv_bfloat16* __restrict__ lo) {
    __shared__ float t[32][33];
    const int nt = blockIdx.x * 32;
    const int kt = blockIdx.y * 32;
    const int tx = threadIdx.x;
    const int ty = threadIdx.y;
#pragma unroll
    for (int i = 0; i < 32; i += 8)
        t[ty + i][tx] = w[(size_t)(kt + ty + i) * ncols + nt + tx];
    __syncthreads();
#pragma unroll
    for (int i = 0; i < 32; i += 8) {
        const float x = t[tx][ty + i];
        const __nv_bfloat16 h = __float2bfloat16(x);
        const size_t o = (size_t)(nt + ty + i) * HDIM + kt + tx;
        hi[o] = h;
        lo[o] = __float2bfloat16(x - __bfloat162float(h));
    }
}

__global__ void convBf16_kernel(const float* __restrict__ w) {
    __shared__ float t[32][33];
    const int nt = blockIdx.x * 32;
    const int kt = blockIdx.y * 32;
    const int tx = threadIdx.x;
    const int ty = threadIdx.y;
#pragma unroll
    for (int i = 0; i < 32; i += 8)
        t[ty + i][tx] = w[(size_t)(kt + ty + i) * VDIM + nt + tx];
    __syncthreads();
#pragma unroll
    for (int i = 0; i < 32; i += 8)
        g_Bf16[(size_t)(nt + ty + i) * HDIM + kt + tx] = __float2half_rn(t[tx][ty + i]);
}

// ---------------- unified split-bf16 HMMA GEMM (128x128 tile) ----------------
#define STAGES 3
#define STAGE_ELEMS (128 * 32)

#define HEPI_BIAS           0
#define HEPI_ELU            1
#define HEPI_ELU_MASK_SPLIT 2
#define HEPI_ACC            3
#define HEPI_ELU_TIMUL      4

template <int EPI, bool GATHER>
__global__ __launch_bounds__(256, 2)
void hmma_gemm(const __nv_bfloat16* __restrict__ Ahi, const __nv_bfloat16* __restrict__ Alo,
               const __nv_bfloat16* __restrict__ Bhi, const __nv_bfloat16* __restrict__ Blo,
               float* __restrict__ C, const float* __restrict__ bias,
               const int* __restrict__ gidx, const float* __restrict__ rowvec,
               __nv_bfloat16* __restrict__ Chi, __nv_bfloat16* __restrict__ Clo,
               const float* __restrict__ aux, int N) {
    __shared__ __align__(16) __nv_bfloat16 sA[STAGES * STAGE_ELEMS];
    __shared__ __align__(16) __nv_bfloat16 sB[STAGES * STAGE_ELEMS];

    const int tid  = threadIdx.x;
    const int lane = tid & 31;
    const int wid  = tid >> 5;
    const int wm   = wid >> 1;
    const int wn   = wid & 1;
    const int bn   = blockIdx.x * 128;
    const int bm   = blockIdx.y * 128;

    const uint32_t sAaddr = smem_u32(sA);
    const uint32_t sBaddr = smem_u32(sB);

    float acc[2][8][4];
#pragma unroll
    for (int t = 0; t < 2; t++)
#pragma unroll
        for (int n = 0; n < 8; n++)
#pragma unroll
            for (int q = 0; q < 4; q++) acc[t][n][q] = 0.0f;

    auto load_stage = [&](int stage, int kt) {
        const int kbase = kt * 16;
#pragma unroll
        for (int i = 0; i < 4; i++) {
            const int id   = tid + i * 256;
            const int isB  = id >> 9;
            const int sub  = id & 511;
            const int half = sub & 1;
            const int r    = (sub >> 1) & 127;
            const int hl   = (sub >> 8) & 1;
            const int c    = hl * 2 + half;
            const __nv_bfloat16* gsrc;
            if (isB) {
                gsrc = (hl ? Blo : Bhi) + (size_t)(bn + r) * HDIM + kbase + half * 8;
            } else {
                const int ar = GATHER ? gidx[bm + r] : (bm + r);
                gsrc = (hl ? Alo : Ahi) + (size_t)ar * HDIM + kbase + half * 8;
            }
            const uint32_t dst = (isB ? sBaddr : sAaddr) +
                (uint32_t)(stage * STAGE_ELEMS + r * 32 + (c ^ ((r >> 1) & 3)) * 8) * 2;
            CP_ASYNC16(dst, gsrc);
        }
    };

    load_stage(0, 0); CP_COMMIT();
    load_stage(1, 1); CP_COMMIT();

    const int a_m  = wm * 32 + (lane & 15);
    const int a_kg = lane >> 4;
    const int b_n  = wn * 64 + (lane & 7) + ((lane >> 4) & 1) * 8;
    const int b_kg = (lane >> 3) & 1;

    for (int kt = 0; kt < HDIM / 16; kt++) {
        const int s = kt % STAGES;
        CP_WAIT1();
        __syncthreads();

        if (kt + 2 < HDIM / 16) load_stage((kt + 2) % STAGES, kt + 2);
        CP_COMMIT();

        const uint32_t baseA = sAaddr + (uint32_t)(s * STAGE_ELEMS) * 2;
        const uint32_t baseB = sBaddr + (uint32_t)(s * STAGE_ELEMS) * 2;

        uint32_t aHi[2][4], aLo[2][4];
#pragma unroll
        for (int t = 0; t < 2; t++) {
            const int r = a_m + t * 16;
            const uint32_t sw = (uint32_t)((r >> 1) & 3);
            LDSM4(aHi[t], baseA + (uint32_t)(r * 32 + ((a_kg       ^ sw)) * 8) * 2);
            LDSM4(aLo[t], baseA + (uint32_t)(r * 32 + (((2 + a_kg) ^ sw)) * 8) * 2);
        }

#pragma unroll
        for (int np = 0; np < 4; np++) {
            const int n = b_n + np * 16;
            const uint32_t sw = (uint32_t)((n >> 1) & 3);
            uint32_t bHi[4], bLo[4];
            LDSM4(bHi, baseB + (uint32_t)(n * 32 + ((b_kg       ^ sw)) * 8) * 2);
            LDSM4(bLo, baseB + (uint32_t)(n * 32 + (((2 + b_kg) ^ sw)) * 8) * 2);
#pragma unroll
            for (int t = 0; t < 2; t++) {
                MMA_BF16(acc[t][2 * np],     aHi[t], bHi[0], bHi[1]);
                MMA_BF16(acc[t][2 * np + 1], aHi[t], bHi[2], bHi[3]);
                MMA_BF16(acc[t][2 * np],     aHi[t], bLo[0], bLo[1]);
                MMA_BF16(acc[t][2 * np + 1], aHi[t], bLo[2], bLo[3]);
                MMA_BF16(acc[t][2 * np],     aLo[t], bHi[0], bHi[1]);
                MMA_BF16(acc[t][2 * np + 1], aLo[t], bHi[2], bHi[3]);
            }
        }
    }

#pragma unroll
    for (int t = 0; t < 2; t++) {
        const int rbase = bm + wm * 32 + t * 16 + (lane >> 2);
#pragma unroll
        for (int ni = 0; ni < 8; ni++) {
            const int col = bn + wn * 64 + ni * 8 + (lane & 3) * 2;
            float bx = 0.0f, by = 0.0f;
            if (EPI != HEPI_ACC) { bx = bias[col]; by = bias[col + 1]; }
#pragma unroll
            for (int h = 0; h < 2; h++) {
                const int row = rbase + h * 8;
                float x = acc[t][ni][2 * h]     + bx;
                float y = acc[t][ni][2 * h + 1] + by;
                float* cp = C + (size_t)row * N + col;
                if (EPI == HEPI_BIAS) {
                    *(float2*)cp = make_float2(x, y);
                } else if (EPI == HEPI_ELU) {
                    *(float2*)cp = make_float2(elu_f(x), elu_f(y));
                } else if (EPI == HEPI_ELU_MASK_SPLIT) {
                    const float mk = rowvec[row];
                    x = elu_f(x) * mk; y = elu_f(y) * mk;
                    *(float2*)cp = make_float2(x, y);
                    const __nv_bfloat16 xh = __float2bfloat16(x);
                    const __nv_bfloat16 yh = __float2bfloat16(y);
                    __nv_bfloat162 vh; vh.x = xh; vh.y = yh;
                    __nv_bfloat162 vl;
                    vl.x = __float2bfloat16(x - __bfloat162float(xh));
                    vl.y = __float2bfloat16(y - __bfloat162float(yh));
                    *(__nv_bfloat162*)(Chi + (size_t)row * HDIM + col) = vh;
                    *(__nv_bfloat162*)(Clo + (size_t)row * HDIM + col) = vl;
                } else if (EPI == HEPI_ACC) {
                    float2 old = *(float2*)cp;
                    *(float2*)cp = make_float2(old.x + x, old.y + y);
                } else if (EPI == HEPI_ELU_TIMUL) {
                    const float* tr = aux + (size_t)gidx[row] * HDIM + col;
                    *(float2*)cp = make_float2(elu_f(x) * tr[0], elu_f(y) * tr[1]);
                }
            }
        }
    }
}

// ---------------- wout GEMM: 2-product split-fp16, k32 stages; pool in epilogue ---
#define WSTAGES 3
#define WA_SUB  (128 * 32)
#define WA_ST   (2 * WA_SUB)
#define WB_ST   (128 * 32)
#define WOUT_SMEM (WSTAGES * (WA_ST + WB_ST) * 2)

__global__ __launch_bounds__(256, 2)
void wout_gemm(const __half* __restrict__ Ahi, const __half* __restrict__ Alo,
               const __half* __restrict__ B,
               float* __restrict__ C, const float* __restrict__ bias,
               const float* __restrict__ rowscale) {
    extern __shared__ __align__(16) __half wsm[];
    __half* sA = wsm;
    __half* sB = wsm + WSTAGES * WA_ST;

    const int tid  = threadIdx.x;
    const int lane = tid & 31;
    const int wid  = tid >> 5;
    const int wm   = wid >> 1;
    const int wn   = wid & 1;
    const int bn   = blockIdx.x * 128;
    const int bm   = blockIdx.y * 128;

    const uint32_t sAaddr = smem_u32(sA);
    const uint32_t sBaddr = smem_u32(sB);

    float acc[2][8][4];
#pragma unroll
    for (int t = 0; t < 2; t++)
#pragma unroll
        for (int n = 0; n < 8; n++)
#pragma unroll
            for (int q = 0; q < 4; q++) acc[t][n][q] = 0.0f;

    auto load_stage = [&](int stage, int st) {
        const int kb = st * 32;
#pragma unroll
        for (int i = 0; i < 4; i++) {
            const int id   = tid + i * 256;
            const int s01  = id >> 9;
            const int sub  = id & 511;
            const int half = sub & 1;
            const int r    = (sub >> 1) & 127;
            const int hl   = (sub >> 8) & 1;
            const int c    = hl * 2 + half;
            const __half* gsrc = (hl ? Alo : Ahi) +
                (size_t)(bm + r) * HDIM + kb + s01 * 16 + half * 8;
            const uint32_t dst = sAaddr +
                (uint32_t)(stage * WA_ST + s01 * WA_SUB + r * 32 + (c ^ ((r >> 1) & 3)) * 8) * 2;
            CP_ASYNC16(dst, gsrc);
        }
#pragma unroll
        for (int i = 0; i < 2; i++) {
            const int id = tid + i * 256;
            const int qc = id & 3;
            const int r  = id >> 2;
            const __half* gsrc = B + (size_t)(bn + r) * HDIM + kb + qc * 8;
            const uint32_t dst = sBaddr +
                (uint32_t)(stage * WB_ST + r * 32 + (qc ^ ((r >> 1) & 3)) * 8) * 2;
            CP_ASYNC16(dst, gsrc);
        }
    };

    load_stage(0, 0); CP_COMMIT();
    load_stage(1, 1); CP_COMMIT();

    const int a_m  = wm * 32 + (lane & 15);
    const int a_kg = lane >> 4;
    const int b_n  = wn * 64 + (lane & 7) + ((lane >> 4) & 1) * 8;
    const int b_kg = (lane >> 3) & 1;

    for (int st = 0; st < HDIM / 32; st++) {
        const int s = st % WSTAGES;
        CP_WAIT1();
        __syncthreads();

        if (st + 2 < HDIM / 32) load_stage((st + 2) % WSTAGES, st + 2);
        CP_COMMIT();

        const uint32_t baseB = sBaddr + (uint32_t)(s * WB_ST) * 2;
#pragma unroll
        for (int hs = 0; hs < 2; hs++) {
            const uint32_t baseA = sAaddr + (uint32_t)(s * WA_ST + hs * WA_SUB) * 2;

            uint32_t aHi[2][4], aLo[2][4];
#pragma unroll
            for (int t = 0; t < 2; t++) {
                const int r = a_m + t * 16;
                const uint32_t sw = (uint32_t)((r >> 1) & 3);
                LDSM4(aHi[t], baseA + (uint32_t)(r * 32 + ((a_kg       ^ sw)) * 8) * 2);
                LDSM4(aLo[t], baseA + (uint32_t)(r * 32 + (((2 + a_kg) ^ sw)) * 8) * 2);
            }

#pragma unroll
            for (int np = 0; np < 4; np++) {
                const int n = b_n + np * 16;
                const uint32_t sw = (uint32_t)((n >> 1) & 3);
                uint32_t bF[4];
                LDSM4(bF, baseB + (uint32_t)(n * 32 + (((hs * 2 + b_kg) ^ sw)) * 8) * 2);
#pragma unroll
                for (int t = 0; t < 2; t++) {
                    MMA_F16(acc[t][2 * np],     aHi[t], bF[0], bF[1]);
                    MMA_F16(acc[t][2 * np + 1], aHi[t], bF[2], bF[3]);
                    MMA_F16(acc[t][2 * np],     aLo[t], bF[0], bF[1]);
                    MMA_F16(acc[t][2 * np + 1], aLo[t], bF[2], bF[3]);
                }
            }
        }
    }

#pragma unroll
    for (int t = 0; t < 2; t++) {
        const int rbase = bm + wm * 32 + t * 16 + (lane >> 2);
        const float p0 = rowscale[rbase];
        const float p1 = rowscale[rbase + 8];
#pragma unroll
        for (int ni = 0; ni < 8; ni++) {
            const int col = bn + wn * 64 + ni * 8 + (lane & 3) * 2;
            const float bx = bias[col], by = bias[col + 1];
            *(float2*)(C + (size_t)rbase * VDIM + col) =
                make_float2(acc[t][ni][0] * p0 + bx, acc[t][ni][1] * p0 + by);
            *(float2*)(C + (size_t)(rbase + 8) * VDIM + col) =
                make_float2(acc[t][ni][2] * p1 + bx, acc[t][ni][3] * p1 + by);
        }
    }
}

// ---------------- attention: 8 rows per block, 2x-unrolled loops ----------------
#define SLP 208
__global__ void attn_kernel() {
    const int i0  = blockIdx.x * 8;
    const int b   = blockIdx.y;
    const int tid = threadIdx.x;
    const int lane = tid & 31;
    const int w   = tid >> 5;

    __shared__ float s_sp[8][SLP];

    for (int j = tid; j < 8 * SLP; j += 256)
        ((float*)s_sp)[j] = -3e38f;
    __syncthreads();

    const int i = i0 + w;
    const int r = b * SL + i;

    float4 h4[4];
#pragma unroll
    for (int k = 0; k < 4; k++)
        h4[k] = *(const float4*)(g_hd3 + (size_t)r * HT3 + lane * 4 + k * 128);

    // logits: 2 j per iteration (independent chains)
    int j = 0;
    for (; j + 1 < i; j += 2) {
        const float* t0 = g_hd3 + (size_t)(b * SL + j) * HT3 + 512;
        const float* t1 = t0 + HT3;
        float s0 = 0.0f, s1 = 0.0f;
#pragma unroll
        for (int k = 0; k < 4; k++) {
            const float4 a4 = *(const float4*)(t0 + lane * 4 + k * 128);
            const float4 b4 = *(const float4*)(t1 + lane * 4 + k * 128);
            s0 = fmaf(h4[k].x, a4.x, s0); s1 = fmaf(h4[k].x, b4.x, s1);
            s0 = fmaf(h4[k].y, a4.y, s0); s1 = fmaf(h4[k].y, b4.y, s1);
            s0 = fmaf(h4[k].z, a4.z, s0); s1 = fmaf(h4[k].z, b4.z, s1);
            s0 = fmaf(h4[k].w, a4.w, s0); s1 = fmaf(h4[k].w, b4.w, s1);
        }
#pragma unroll
        for (int o = 16; o > 0; o >>= 1) {
            s0 += __shfl_xor_sync(0xffffffff, s0, o);
            s1 += __shfl_xor_sync(0xffffffff, s1, o);
        }
        if (lane == 0) {
            if (g_rowmask[b * SL + j] > 0.5f)     s_sp[w][j] = s0;
            if (g_rowmask[b * SL + j + 1] > 0.5f) s_sp[w][j + 1] = s1;
        }
    }
    if (j < i) {
        const float* t0 = g_hd3 + (size_t)(b * SL + j) * HT3 + 512;
        float s0 = 0.0f;
#pragma unroll
        for (int k = 0; k < 4; k++) {
            const float4 a4 = *(const float4*)(t0 + lane * 4 + k * 128);
            s0 = fmaf(h4[k].x, a4.x, s0);
            s0 = fmaf(h4[k].y, a4.y, s0);
            s0 = fmaf(h4[k].z, a4.z, s0);
            s0 = fmaf(h4[k].w, a4.w, s0);
        }
#pragma unroll
        for (int o = 16; o > 0; o >>= 1) s0 += __shfl_xor_sync(0xffffffff, s0, o);
        if (lane == 0 && g_rowmask[b * SL + j] > 0.5f) s_sp[w][j] = s0;
    }

    // softmax of row w
    {
        float m = -3e38f;
        for (int jj = lane; jj < SL; jj += 32) m = fmaxf(m, s_sp[w][jj]);
#pragma unroll
        for (int o = 16; o > 0; o >>= 1) m = fmaxf(m, __shfl_xor_sync(0xffffffff, m, o));
        float sum = 0.0f;
        float ev[7];
#pragma unroll
        for (int q = 0; q < 7; q++) {
            const int jj = lane + q * 32;
            float e = 0.0f;
            if (jj < SL) {
                const float v = s_sp[w][jj];
                if (v > -1e37f) e = expf(v - m);
            }
            ev[q] = e;
            sum += e;
        }
#pragma unroll
        for (int o = 16; o > 0; o >>= 1) sum += __shfl_xor_sync(0xffffffff, sum, o);
        const float inv = (sum > 0.0f) ? 1.0f / sum : 0.0f;
#pragma unroll
        for (int q = 0; q < 7; q++) {
            const int jj = lane + q * 32;
            if (jj < SL) s_sp[w][jj] = ev[q] * inv;
        }
    }
    __syncthreads();

    // depend: 2 j per iteration
    const int c2 = tid * 2;
    float2 acc[8];
#pragma unroll
    for (int ii = 0; ii < 8; ii++) acc[ii] = make_float2(0.0f, 0.0f);

    const int jmax = i0 + 7;
    int jj = 0;
    for (; jj + 1 < jmax; jj += 2) {
        const float2 hv0 = *(const float2*)(g_hidden + (size_t)(b * SL + jj) * HDIM + c2);
        const float2 hv1 = *(const float2*)(g_hidden + (size_t)(b * SL + jj + 1) * HDIM + c2);
#pragma unroll
        for (int ii = 0; ii < 8; ii++) {
            const float s0 = s_sp[ii][jj];
            const float s1 = s_sp[ii][jj + 1];
            acc[ii].x = fmaf(s0, hv0.x, fmaf(s1, hv1.x, acc[ii].x));
            acc[ii].y = fmaf(s0, hv0.y, fmaf(s1, hv1.y, acc[ii].y));
        }
    }
    if (jj < jmax) {
        const float2 hv0 = *(const float2*)(g_hidden + (size_t)(b * SL + jj) * HDIM + c2);
#pragma unroll
        for (int ii = 0; ii < 8; ii++) {
            const float s0 = s_sp[ii][jj];
            acc[ii].x = fmaf(s0, hv0.x, acc[ii].x);
            acc[ii].y = fmaf(s0, hv0.y, acc[ii].y);
        }
    }

#pragma unroll
    for (int ii = 0; ii < 8; ii++) {
        const size_t o = (size_t)(b * SL + i0 + ii) * HDIM + c2;
        *(float2*)(g_depend + o) = acc[ii];
        const __nv_bfloat16 hx = __float2bfloat16(acc[ii].x);
        const __nv_bfloat16 hy = __float2bfloat16(acc[ii].y);
        __nv_bfloat162 vh; vh.x = hx; vh.y = hy;
        __nv_bfloat162 vl;
        vl.x = __float2bfloat16(acc[ii].x - __bfloat162float(hx));
        vl.y = __float2bfloat16(acc[ii].y - __bfloat162float(hy));
        *(__nv_bfloat162*)(g_depHi + o) = vh;
        *(__nv_bfloat162*)(g_depLo + o) = vl;
    }
}

// ---------------- gate blend: emits bf16 split (m1 GEMM) + fp16 split (wout) -------
__global__ void enc_kernel() {
    const int idx = blockIdx.x * 256 + threadIdx.x;
    const int row = idx >> 9;
    const int col = idx & 511;
    const float gv = g_hd3[(size_t)row * HT3 + 1024 + col];
    const float g = 1.0f / (1.0f + expf(-gv));
    const float x = (g * g_hidden[idx] + (1.0f - g) * g_depend[idx]) * g_rowmask[row];
    const __nv_bfloat16 h = __float2bfloat16(x);
    g_encHi[idx] = h;
    g_encLo[idx] = __float2bfloat16(x - __bfloat162float(h));
    const __half hf = __float2half_rn(x);
    g_Af16hi[idx] = hf;
    g_Af16lo[idx] = __float2half_rn(x - __half2float(hf));
}

// ---------------- map2 + pool softmax ----------------
__global__ void pool_kernel(const float* __restrict__ wm2, const float* __restrict__ bm2) {
    const int b = blockIdx.x;
    const int tid = threadIdx.x;
    const int lane = tid & 31;
    const int warp = tid >> 5;

    __shared__ float sm2[SL];
    __shared__ float rbuf[256];

    for (int i = warp; i < SL; i += 8) {
        const float* mr = g_m1 + (size_t)(b * SL + i) * HDIM;
        float s = 0.0f;
        for (int k = lane; k < HDIM; k += 32) s = fmaf(mr[k], wm2[k], s);
#pragma unroll
        for (int o = 16; o > 0; o >>= 1) s += __shfl_xor_sync(0xffffffff, s, o);
        if (lane == 0) sm2[i] = s + bm2[0];
    }
    __syncthreads();

    const bool valid = (tid < SL) && (g_rowmask[b * SL + tid] > 0.5f);
    float v = valid ? sm2[tid] : -3e38f;
    rbuf[tid] = v;
    __syncthreads();
    for (int s = 128; s > 0; s >>= 1) {
        if (tid < s) rbuf[tid] = fmaxf(rbuf[tid], rbuf[tid + s]);
        __syncthreads();
    }
    const float m = rbuf[0];
    __syncthreads();
    float e = valid ? expf(sm2[tid] - m) : 0.0f;
    rbuf[tid] = e;
    __syncthreads();
    for (int s = 128; s > 0; s >>= 1) {
        if (tid < s) rbuf[tid] += rbuf[tid + s];
        __syncthreads();
    }
    const float ssum = rbuf[0];
    if (tid < SL) g_pool[b * SL + tid] = (ssum > 0.0f) ? e / ssum : 0.0f;
}

// ---------------- launch ----------------
extern "C" void kernel_launch(void* const* d_in, const int* in_sizes, int n_in,
                              void* d_out, int out_size) {
    const int*   cas  = (const int*)d_in[0];
    const int*   tiiv = (const int*)d_in[1];
    const float* emb  = (const float*)d_in[2];
    const float* tl   = (const float*)d_in[3];
    const float* w1   = (const float*)d_in[4];
    const float* b1   = (const float*)d_in[5];
    const float* wh   = (const float*)d_in[6];
    const float* bh   = (const float*)d_in[7];
    const float* wt   = (const float*)d_in[8];
    const float* bt   = (const float*)d_in[9];
    const float* wg   = (const float*)d_in[10];
    const float* bg   = (const float*)d_in[11];
    const float* wm1  = (const float*)d_in[12];
    const float* bm1  = (const float*)d_in[13];
    const float* wti  = (const float*)d_in[14];
    const float* bti  = (const float*)d_in[15];
    const float* wm2  = (const float*)d_in[16];
    const float* bm2  = (const float*)d_in[17];
    const float* wout = (const float*)d_in[18];
    const float* bout = (const float*)d_in[19];
    float* out = (float*)d_out;

    float *hiddenP, *hd3P, *m1P, *rowmaskP, *tiP, *bias3P, *poolP;
    int *tidxP;
    __nv_bfloat16 *casHiP, *casLoP, *tlHiP, *tlLoP, *hidHiP, *hidLoP, *depHiP, *depLoP;
    __nv_bfloat16 *encHiP, *encLoP, *wTHiP, *wTLoP;
    __half *Af16hiP, *Af16loP, *Bf16P;
    cudaGetSymbolAddress((void**)&hiddenP, g_hidden);
    cudaGetSymbolAddress((void**)&hd3P,    g_hd3);
    cudaGetSymbolAddress((void**)&m1P,     g_m1);
    cudaGetSymbolAddress((void**)&rowmaskP,g_rowmask);
    cudaGetSymbolAddress((void**)&tiP,     g_ti);
    cudaGetSymbolAddress((void**)&bias3P,  g_bias3);
    cudaGetSymbolAddress((void**)&poolP,   g_pool);
    cudaGetSymbolAddress((void**)&tidxP,   g_tidx);
    cudaGetSymbolAddress((void**)&casHiP,  g_casHi);
    cudaGetSymbolAddress((void**)&casLoP,  g_casLo);
    cudaGetSymbolAddress((void**)&tlHiP,   g_tlHi);
    cudaGetSymbolAddress((void**)&tlLoP,   g_tlLo);
    cudaGetSymbolAddress((void**)&hidHiP,  g_hidHi);
    cudaGetSymbolAddress((void**)&hidLoP,  g_hidLo);
    cudaGetSymbolAddress((void**)&depHiP,  g_depHi);
    cudaGetSymbolAddress((void**)&depLoP,  g_depLo);
    cudaGetSymbolAddress((void**)&encHiP,  g_encHi);
    cudaGetSymbolAddress((void**)&encLoP,  g_encLo);
    cudaGetSymbolAddress((void**)&wTHiP,   g_wTHi);
    cudaGetSymbolAddress((void**)&wTLoP,   g_wTLo);
    cudaGetSymbolAddress((void**)&Af16hiP, g_Af16hi);
    cudaGetSymbolAddress((void**)&Af16loP, g_Af16lo);
    cudaGetSymbolAddress((void**)&Bf16P,   g_Bf16);

    cudaFuncSetAttribute(wout_gemm, cudaFuncAttributeMaxDynamicSharedMemorySize, WOUT_SMEM);

    prep_kernel<<<BBATCH, 256>>>(cas, tiiv);
    bias3_kernel<<<6, 256>>>(bh, bt, bg);

    // operand prep
    gatherSplit_kernel<<<(MROWS * HDIM) / 256, 256>>>(emb);
    split_kernel<<<(TDIM * HDIM + 255) / 256, 256>>>(tl, tlHiP, tlLoP, TDIM * HDIM);
    dim3 cT(16, 16), cB(32, 8);
    convT_kernel<<<cT, cB>>>(w1,  HDIM, wTHiP + 0 * WSLOT, wTLoP + 0 * WSLOT);
    convT_kernel<<<cT, cB>>>(wh,  HDIM, wTHiP + 1 * WSLOT, wTLoP + 1 * WSLOT);
    convT_kernel<<<cT, cB>>>(wt,  HDIM, wTHiP + 2 * WSLOT, wTLoP + 2 * WSLOT);
    convT_kernel<<<cT, cB>>>(wg,  HDIM, wTHiP + 3 * WSLOT, wTLoP + 3 * WSLOT);
    convT_kernel<<<cT, cB>>>(wg + (size_t)HDIM * HDIM, HDIM,
                             wTHiP + 4 * WSLOT, wTLoP + 4 * WSLOT);
    convT_kernel<<<cT, cB>>>(wm1, HDIM, wTHiP + 5 * WSLOT, wTLoP + 5 * WSLOT);
    convT_kernel<<<cT, cB>>>(wti, HDIM, wTHiP + 6 * WSLOT, wTLoP + 6 * WSLOT);
    convBf16_kernel<<<dim3(VDIM / 32, 16), cB>>>(wout);

    dim3 gH(HDIM / 128, MROWS / 128);     // (4, 50)
    dim3 gHT3(HT3 / 128, MROWS / 128);    // (12, 50)
    dim3 gV(VDIM / 128, MROWS / 128);     // (250, 50)

    // hidden = elu(cas_emb @ w1 + b1) * rowmask  (+ fused split)
    hmma_gemm<HEPI_ELU_MASK_SPLIT, false><<<gH, 256>>>(
        casHiP, casLoP, wTHiP + 0 * WSLOT, wTLoP + 0 * WSLOT,
        hiddenP, b1, nullptr, rowmaskP, hidHiP, hidLoP, nullptr, HDIM);

    // fused [head|tail|gbuf] = hidden @ [wh|wt|wg1]^T + bias3  (N=1536)
    hmma_gemm<HEPI_BIAS, false><<<gHT3, 256>>>(
        hidHiP, hidLoP, wTHiP + 1 * WSLOT, wTLoP + 1 * WSLOT,
        hd3P, bias3P, nullptr, nullptr, nullptr, nullptr, nullptr, HT3);

    // ti (101 distinct time rows, padded to 128): elu(tl @ wti + bti)
    hmma_gemm<HEPI_ELU, false><<<dim3(4, 1), 256>>>(
        tlHiP, tlLoP, wTHiP + 6 * WSLOT, wTLoP + 6 * WSLOT,
        tiP, bti, nullptr, nullptr, nullptr, nullptr, nullptr, HDIM);

    // attention -> depend (+ fused split), 8 rows/block
    attn_kernel<<<dim3(SL / 8, BBATCH), 256>>>();

    // gbuf += depend @ wg2^T
    hmma_gemm<HEPI_ACC, false><<<gH, 256>>>(
        depHiP, depLoP, wTHiP + 4 * WSLOT, wTLoP + 4 * WSLOT,
        hd3P + 1024, nullptr, nullptr, nullptr, nullptr, nullptr, nullptr, HT3);

    // enc blend (+ fused bf16 AND fp16 splits)
    enc_kernel<<<(MROWS * HDIM) / 256, 256>>>();

    // m1 = elu(enc@wm1 + bm1) * ti[tidx[row]]
    hmma_gemm<HEPI_ELU_TIMUL, false><<<gH, 256>>>(
        encHiP, encLoP, wTHiP + 5 * WSLOT, wTLoP + 5 * WSLOT,
        m1P, bm1, tidxP, nullptr, nullptr, nullptr, tiP, HDIM);

    // pool softmax over sequence
    pool_kernel<<<BBATCH, 256>>>(wm2, bm2);

    // logits_out = pool ⊙ (enc @ fp16(wout)^T) + bout
    wout_gemm<<<gV, 256, WOUT_SMEM>>>(Af16hiP, Af16loP, Bf16P, out, bout, poolP);
}

// round 16
// speedup vs baseline: 1.4918x; 1.4918x over previous
#include <cuda_runtime.h>
#include <cuda_bf16.h>
#include <cuda_fp16.h>
#include <math.h>
#include <stdint.h>

// Problem constants
#define BBATCH 32
#define SFULL  201
#define SL     200
#define HDIM   512
#define EDIM   512
#define VDIM   32000
#define TDIM   101
#define MROWS  (BBATCH * SL)   // 6400
#define HT3    1536            // head|tail|gate fused width

// ---------------- scratch (device globals; no allocation allowed) ----------------
__device__ float g_hidden[MROWS * HDIM];
__device__ float g_hd3   [MROWS * HT3];     // [head | tail | gbuf] fused
__device__ float g_enc   [MROWS * HDIM];
__device__ float g_m1    [MROWS * HDIM];
__device__ float g_depend[MROWS * HDIM];
__device__ float g_ti    [128 * HDIM];      // elu(tl@wti+bti), 101 rows (pad 128)
__device__ float g_bias3 [HT3];
__device__ float g_rowmask[MROWS];
__device__ float g_pool  [MROWS];
__device__ int   g_gidx  [MROWS];
__device__ int   g_tidx  [MROWS];

// split-bf16 operand buffers (H-dim stages)
__device__ __nv_bfloat16 g_casHi[MROWS * HDIM];
__device__ __nv_bfloat16 g_casLo[MROWS * HDIM];
__device__ __nv_bfloat16 g_tlHi[128 * HDIM];   // pad 101 -> 128 (zeros beyond)
__device__ __nv_bfloat16 g_tlLo[128 * HDIM];
__device__ __nv_bfloat16 g_hidHi[MROWS * HDIM];
__device__ __nv_bfloat16 g_hidLo[MROWS * HDIM];
__device__ __nv_bfloat16 g_depHi[MROWS * HDIM];
__device__ __nv_bfloat16 g_depLo[MROWS * HDIM];
__device__ __nv_bfloat16 g_encHi[MROWS * HDIM];
__device__ __nv_bfloat16 g_encLo[MROWS * HDIM];
// 7 transposed/split weights [512,512]: w1(0), wh(1), wt(2), wg1(3), wg2(4), wm1(5), wti(6)
// slots 1..3 contiguous -> fused [1536, 512] B for the triple GEMM
#define WSLOT (HDIM * HDIM)
__device__ __nv_bfloat16 g_wTHi[7 * WSLOT];
__device__ __nv_bfloat16 g_wTLo[7 * WSLOT];

// split-fp16 operands for the wout GEMM (2-product scheme)
__device__ __half g_Af16hi[MROWS * HDIM];
__device__ __half g_Af16lo[MROWS * HDIM];
__device__ __half g_Bf16[(size_t)VDIM * HDIM];

// ---------------- base-PTX helpers (target is plain sm_103: no tcgen05!) --------
__device__ __forceinline__ uint32_t smem_u32(const void* p) {
    uint32_t a;
    asm("{ .reg .u64 t; cvta.to.shared.u64 t, %1; cvt.u32.u64 %0, t; }" : "=r"(a) : "l"(p));
    return a;
}

#define CP_ASYNC16(dst, src) \
    asm volatile("cp.async.cg.shared.global [%0], [%1], 16;" :: "r"(dst), "l"(src))
#define CP_COMMIT() asm volatile("cp.async.commit_group;" ::: "memory")
#define CP_WAIT1()  asm volatile("cp.async.wait_group 1;" ::: "memory")

#define LDSM4(r, addr)                                                        \
    asm volatile("ldmatrix.sync.aligned.m8n8.x4.shared.b16 {%0,%1,%2,%3}, [%4];" \
                 : "=r"((r)[0]), "=r"((r)[1]), "=r"((r)[2]), "=r"((r)[3])     \
                 : "r"(addr))

#define MMA_BF16(d, a, b0, b1)                                                \
    asm volatile("mma.sync.aligned.m16n8k16.row.col.f32.bf16.bf16.f32 "       \
                 "{%0,%1,%2,%3}, {%4,%5,%6,%7}, {%8,%9}, {%0,%1,%2,%3};"      \
                 : "+f"((d)[0]), "+f"((d)[1]), "+f"((d)[2]), "+f"((d)[3])     \
                 : "r"((a)[0]), "r"((a)[1]), "r"((a)[2]), "r"((a)[3]),        \
                   "r"(b0), "r"(b1))

#define MMA_F16(d, a, b0, b1)                                                 \
    asm volatile("mma.sync.aligned.m16n8k16.row.col.f32.f16.f16.f32 "         \
                 "{%0,%1,%2,%3}, {%4,%5,%6,%7}, {%8,%9}, {%0,%1,%2,%3};"      \
                 : "+f"((d)[0]), "+f"((d)[1]), "+f"((d)[2]), "+f"((d)[3])     \
                 : "r"((a)[0]), "r"((a)[1]), "r"((a)[2]), "r"((a)[3]),        \
                   "r"(b0), "r"(b1))

__device__ __forceinline__ float elu_f(float x) { return x > 0.0f ? x : expm1f(x); }

// ---------------- prep ----------------
__global__ void prep_kernel(const int* __restrict__ cas, const int* __restrict__ tii) {
    int b = blockIdx.x;
    int tid = threadIdx.x;
    __shared__ int red[256];
    int cnt = 0;
    for (int i = tid; i < SL; i += 256) cnt += (cas[b * SFULL + i] != 0);
    red[tid] = cnt;
    __syncthreads();
    for (int s = 128; s > 0; s >>= 1) {
        if (tid < s) red[tid] += red[tid + s];
        __syncthreads();
    }
    int len = red[0];
    for (int i = tid; i < SL; i += 256) {
        int r = b * SL + i;
        g_rowmask[r] = (i < len) ? 1.0f : 0.0f;
        g_gidx[r] = cas[b * SFULL + i];
        g_tidx[r] = tii[b * SFULL + i];
    }
}

__global__ void bias3_kernel(const float* __restrict__ bh, const float* __restrict__ bt,
                             const float* __restrict__ bg) {
    const int i = blockIdx.x * 256 + threadIdx.x;
    if (i >= HT3) return;
    g_bias3[i] = (i < 512) ? bh[i] : (i < 1024) ? bt[i - 512] : bg[i - 1024];
}

// ---------------- gather + split embedding rows ----------------
__global__ void gatherSplit_kernel(const float* __restrict__ emb) {
    const int idx = blockIdx.x * 256 + threadIdx.x;
    const int row = idx >> 9;
    const int col = idx & 511;
    const float x = emb[(size_t)g_gidx[row] * EDIM + col];
    const __nv_bfloat16 h = __float2bfloat16(x);
    g_casHi[idx] = h;
    g_casLo[idx] = __float2bfloat16(x - __bfloat162float(h));
}

__global__ void split_kernel(const float* __restrict__ src, __nv_bfloat16* __restrict__ hi,
                             __nv_bfloat16* __restrict__ lo, int n) {
    const int idx = blockIdx.x * 256 + threadIdx.x;
    if (idx >= n) return;
    const float x = src[idx];
    const __nv_bfloat16 h = __float2bfloat16(x);
    hi[idx] = h;
    lo[idx] = __float2bfloat16(x - __bfloat162float(h));
}

// ---------------- transpose + split (bf16) ----------------
__global__ void convT_kernel(const float* __restrict__ w, int ncols,
                             __nv_bfloat16* __restrict__ hi, __nv_bfloat16* __restrict__ lo) {
    __shared__ float t[32][33];
    const int nt = blockIdx.x * 32;
    const int kt = blockIdx.y * 32;
    const int tx = threadIdx.x;
    const int ty = threadIdx.y;
#pragma unroll
    for (int i = 0; i < 32; i += 8)
        t[ty + i][tx] = w[(size_t)(kt + ty + i) * ncols + nt + tx];
    __syncthreads();
#pragma unroll
    for (int i = 0; i < 32; i += 8) {
        const float x = t[tx][ty + i];
        const __nv_bfloat16 h = __float2bfloat16(x);
        const size_t o = (size_t)(nt + ty + i) * HDIM + kt + tx;
        hi[o] = h;
        lo[o] = __float2bfloat16(x - __bfloat162float(h));
    }
}

__global__ void convBf16_kernel(const float* __restrict__ w) {
    __shared__ float t[32][33];
    const int nt = blockIdx.x * 32;
    const int kt = blockIdx.y * 32;
    const int tx = threadIdx.x;
    const int ty = threadIdx.y;
#pragma unroll
    for (int i = 0; i < 32; i += 8)
        t[ty + i][tx] = w[(size_t)(kt + ty + i) * VDIM + nt + tx];
    __syncthreads();
#pragma unroll
    for (int i = 0; i < 32; i += 8)
        g_Bf16[(size_t)(nt + ty + i) * HDIM + kt + tx] = __float2half_rn(t[tx][ty + i]);
}

// ---------------- unified split-bf16 HMMA GEMM (128x128 tile) ----------------
#define STAGES 3
#define STAGE_ELEMS (128 * 32)

#define HEPI_BIAS           0
#define HEPI_ELU            1
#define HEPI_ELU_MASK_SPLIT 2
#define HEPI_ACC            3
#define HEPI_ELU_TIMUL      4   // C = elu(acc+bias) * aux[gidx[row]*512 + col]

template <int EPI, bool GATHER>
__global__ __launch_bounds__(256, 2)
void hmma_gemm(const __nv_bfloat16* __restrict__ Ahi, const __nv_bfloat16* __restrict__ Alo,
               const __nv_bfloat16* __restrict__ Bhi, const __nv_bfloat16* __restrict__ Blo,
               float* __restrict__ C, const float* __restrict__ bias,
               const int* __restrict__ gidx, const float* __restrict__ rowvec,
               __nv_bfloat16* __restrict__ Chi, __nv_bfloat16* __restrict__ Clo,
               const float* __restrict__ aux, int N) {
    __shared__ __align__(16) __nv_bfloat16 sA[STAGES * STAGE_ELEMS];
    __shared__ __align__(16) __nv_bfloat16 sB[STAGES * STAGE_ELEMS];

    const int tid  = threadIdx.x;
    const int lane = tid & 31;
    const int wid  = tid >> 5;
    const int wm   = wid >> 1;
    const int wn   = wid & 1;
    const int bn   = blockIdx.x * 128;
    const int bm   = blockIdx.y * 128;

    const uint32_t sAaddr = smem_u32(sA);
    const uint32_t sBaddr = smem_u32(sB);

    float acc[2][8][4];
#pragma unroll
    for (int t = 0; t < 2; t++)
#pragma unroll
        for (int n = 0; n < 8; n++)
#pragma unroll
            for (int q = 0; q < 4; q++) acc[t][n][q] = 0.0f;

    auto load_stage = [&](int stage, int kt) {
        const int kbase = kt * 16;
#pragma unroll
        for (int i = 0; i < 4; i++) {
            const int id   = tid + i * 256;
            const int isB  = id >> 9;
            const int sub  = id & 511;
            const int half = sub & 1;
            const int r    = (sub >> 1) & 127;
            const int hl   = (sub >> 8) & 1;
            const int c    = hl * 2 + half;
            const __nv_bfloat16* gsrc;
            if (isB) {
                gsrc = (hl ? Blo : Bhi) + (size_t)(bn + r) * HDIM + kbase + half * 8;
            } else {
                const int ar = GATHER ? gidx[bm + r] : (bm + r);
                gsrc = (hl ? Alo : Ahi) + (size_t)ar * HDIM + kbase + half * 8;
            }
            const uint32_t dst = (isB ? sBaddr : sAaddr) +
                (uint32_t)(stage * STAGE_ELEMS + r * 32 + (c ^ ((r >> 1) & 3)) * 8) * 2;
            CP_ASYNC16(dst, gsrc);
        }
    };

    load_stage(0, 0); CP_COMMIT();
    load_stage(1, 1); CP_COMMIT();

    const int a_m  = wm * 32 + (lane & 15);
    const int a_kg = lane >> 4;
    const int b_n  = wn * 64 + (lane & 7) + ((lane >> 4) & 1) * 8;
    const int b_kg = (lane >> 3) & 1;

    for (int kt = 0; kt < HDIM / 16; kt++) {
        const int s = kt % STAGES;
        CP_WAIT1();
        __syncthreads();

        if (kt + 2 < HDIM / 16) load_stage((kt + 2) % STAGES, kt + 2);
        CP_COMMIT();

        const uint32_t baseA = sAaddr + (uint32_t)(s * STAGE_ELEMS) * 2;
        const uint32_t baseB = sBaddr + (uint32_t)(s * STAGE_ELEMS) * 2;

        uint32_t aHi[2][4], aLo[2][4];
#pragma unroll
        for (int t = 0; t < 2; t++) {
            const int r = a_m + t * 16;
            const uint32_t sw = (uint32_t)((r >> 1) & 3);
            LDSM4(aHi[t], baseA + (uint32_t)(r * 32 + ((a_kg       ^ sw)) * 8) * 2);
            LDSM4(aLo[t], baseA + (uint32_t)(r * 32 + (((2 + a_kg) ^ sw)) * 8) * 2);
        }

#pragma unroll
        for (int np = 0; np < 4; np++) {
            const int n = b_n + np * 16;
            const uint32_t sw = (uint32_t)((n >> 1) & 3);
            uint32_t bHi[4], bLo[4];
            LDSM4(bHi, baseB + (uint32_t)(n * 32 + ((b_kg       ^ sw)) * 8) * 2);
            LDSM4(bLo, baseB + (uint32_t)(n * 32 + (((2 + b_kg) ^ sw)) * 8) * 2);
#pragma unroll
            for (int t = 0; t < 2; t++) {
                MMA_BF16(acc[t][2 * np],     aHi[t], bHi[0], bHi[1]);
                MMA_BF16(acc[t][2 * np + 1], aHi[t], bHi[2], bHi[3]);
                MMA_BF16(acc[t][2 * np],     aHi[t], bLo[0], bLo[1]);
                MMA_BF16(acc[t][2 * np + 1], aHi[t], bLo[2], bLo[3]);
                MMA_BF16(acc[t][2 * np],     aLo[t], bHi[0], bHi[1]);
                MMA_BF16(acc[t][2 * np + 1], aLo[t], bHi[2], bHi[3]);
            }
        }
    }

#pragma unroll
    for (int t = 0; t < 2; t++) {
        const int rbase = bm + wm * 32 + t * 16 + (lane >> 2);
#pragma unroll
        for (int ni = 0; ni < 8; ni++) {
            const int col = bn + wn * 64 + ni * 8 + (lane & 3) * 2;
            float bx = 0.0f, by = 0.0f;
            if (EPI != HEPI_ACC) { bx = bias[col]; by = bias[col + 1]; }
#pragma unroll
            for (int h = 0; h < 2; h++) {
                const int row = rbase + h * 8;
                float x = acc[t][ni][2 * h]     + bx;
                float y = acc[t][ni][2 * h + 1] + by;
                float* cp = C + (size_t)row * N + col;
                if (EPI == HEPI_BIAS) {
                    *(float2*)cp = make_float2(x, y);
                } else if (EPI == HEPI_ELU) {
                    *(float2*)cp = make_float2(elu_f(x), elu_f(y));
                } else if (EPI == HEPI_ELU_MASK_SPLIT) {
                    const float mk = rowvec[row];
                    x = elu_f(x) * mk; y = elu_f(y) * mk;
                    *(float2*)cp = make_float2(x, y);
                    const __nv_bfloat16 xh = __float2bfloat16(x);
                    const __nv_bfloat16 yh = __float2bfloat16(y);
                    __nv_bfloat162 vh; vh.x = xh; vh.y = yh;
                    __nv_bfloat162 vl;
                    vl.x = __float2bfloat16(x - __bfloat162float(xh));
                    vl.y = __float2bfloat16(y - __bfloat162float(yh));
                    *(__nv_bfloat162*)(Chi + (size_t)row * HDIM + col) = vh;
                    *(__nv_bfloat162*)(Clo + (size_t)row * HDIM + col) = vl;
                } else if (EPI == HEPI_ACC) {
                    float2 old = *(float2*)cp;
                    *(float2*)cp = make_float2(old.x + x, old.y + y);
                } else if (EPI == HEPI_ELU_TIMUL) {
                    const float* tr = aux + (size_t)gidx[row] * HDIM + col;
                    *(float2*)cp = make_float2(elu_f(x) * tr[0], elu_f(y) * tr[1]);
                }
            }
        }
    }
}

// ---------------- wout GEMM: 2-product split-fp16, k32 stages (proven R10) --------
#define WSTAGES 3
#define WA_SUB  (128 * 32)
#define WA_ST   (2 * WA_SUB)
#define WB_ST   (128 * 32)
#define WOUT_SMEM (WSTAGES * (WA_ST + WB_ST) * 2)

__global__ __launch_bounds__(256, 2)
void wout_gemm(const __half* __restrict__ Ahi, const __half* __restrict__ Alo,
               const __half* __restrict__ B,
               float* __restrict__ C, const float* __restrict__ bias) {
    extern __shared__ __align__(16) __half wsm[];
    __half* sA = wsm;
    __half* sB = wsm + WSTAGES * WA_ST;

    const int tid  = threadIdx.x;
    const int lane = tid & 31;
    const int wid  = tid >> 5;
    const int wm   = wid >> 1;
    const int wn   = wid & 1;
    const int bn   = blockIdx.x * 128;
    const int bm   = blockIdx.y * 128;

    const uint32_t sAaddr = smem_u32(sA);
    const uint32_t sBaddr = smem_u32(sB);

    float acc[2][8][4];
#pragma unroll
    for (int t = 0; t < 2; t++)
#pragma unroll
        for (int n = 0; n < 8; n++)
#pragma unroll
            for (int q = 0; q < 4; q++) acc[t][n][q] = 0.0f;

    auto load_stage = [&](int stage, int st) {
        const int kb = st * 32;
#pragma unroll
        for (int i = 0; i < 4; i++) {
            const int id   = tid + i * 256;
            const int s01  = id >> 9;
            const int sub  = id & 511;
            const int half = sub & 1;
            const int r    = (sub >> 1) & 127;
            const int hl   = (sub >> 8) & 1;
            const int c    = hl * 2 + half;
            const __half* gsrc = (hl ? Alo : Ahi) +
                (size_t)(bm + r) * HDIM + kb + s01 * 16 + half * 8;
            const uint32_t dst = sAaddr +
                (uint32_t)(stage * WA_ST + s01 * WA_SUB + r * 32 + (c ^ ((r >> 1) & 3)) * 8) * 2;
            CP_ASYNC16(dst, gsrc);
        }
#pragma unroll
        for (int i = 0; i < 2; i++) {
            const int id = tid + i * 256;
            const int qc = id & 3;
            const int r  = id >> 2;
            const __half* gsrc = B + (size_t)(bn + r) * HDIM + kb + qc * 8;
            const uint32_t dst = sBaddr +
                (uint32_t)(stage * WB_ST + r * 32 + (qc ^ ((r >> 1) & 3)) * 8) * 2;
            CP_ASYNC16(dst, gsrc);
        }
    };

    load_stage(0, 0); CP_COMMIT();
    load_stage(1, 1); CP_COMMIT();

    const int a_m  = wm * 32 + (lane & 15);
    const int a_kg = lane >> 4;
    const int b_n  = wn * 64 + (lane & 7) + ((lane >> 4) & 1) * 8;
    const int b_kg = (lane >> 3) & 1;

    for (int st = 0; st < HDIM / 32; st++) {
        const int s = st % WSTAGES;
        CP_WAIT1();
        __syncthreads();

        if (st + 2 < HDIM / 32) load_stage((st + 2) % WSTAGES, st + 2);
        CP_COMMIT();

        const uint32_t baseB = sBaddr + (uint32_t)(s * WB_ST) * 2;
#pragma unroll
        for (int hs = 0; hs < 2; hs++) {
            const uint32_t baseA = sAaddr + (uint32_t)(s * WA_ST + hs * WA_SUB) * 2;

            uint32_t aHi[2][4], aLo[2][4];
#pragma unroll
            for (int t = 0; t < 2; t++) {
                const int r = a_m + t * 16;
                const uint32_t sw = (uint32_t)((r >> 1) & 3);
                LDSM4(aHi[t], baseA + (uint32_t)(r * 32 + ((a_kg       ^ sw)) * 8) * 2);
                LDSM4(aLo[t], baseA + (uint32_t)(r * 32 + (((2 + a_kg) ^ sw)) * 8) * 2);
            }

#pragma unroll
            for (int np = 0; np < 4; np++) {
                const int n = b_n + np * 16;
                const uint32_t sw = (uint32_t)((n >> 1) & 3);
                uint32_t bF[4];
                LDSM4(bF, baseB + (uint32_t)(n * 32 + (((hs * 2 + b_kg) ^ sw)) * 8) * 2);
#pragma unroll
                for (int t = 0; t < 2; t++) {
                    MMA_F16(acc[t][2 * np],     aHi[t], bF[0], bF[1]);
                    MMA_F16(acc[t][2 * np + 1], aHi[t], bF[2], bF[3]);
                    MMA_F16(acc[t][2 * np],     aLo[t], bF[0], bF[1]);
                    MMA_F16(acc[t][2 * np + 1], aLo[t], bF[2], bF[3]);
                }
            }
        }
    }

#pragma unroll
    for (int t = 0; t < 2; t++) {
        const int rbase = bm + wm * 32 + t * 16 + (lane >> 2);
#pragma unroll
        for (int ni = 0; ni < 8; ni++) {
            const int col = bn + wn * 64 + ni * 8 + (lane & 3) * 2;
            const float bx = bias[col], by = bias[col + 1];
#pragma unroll
            for (int h = 0; h < 2; h++) {
                const int row = rbase + h * 8;
                *(float2*)(C + (size_t)row * VDIM + col) =
                    make_float2(acc[t][ni][2 * h] + bx, acc[t][ni][2 * h + 1] + by);
            }
        }
    }
}

// ---------------- attention: 8 rows per block ----------------
#define SLP 208
__global__ void attn_kernel() {
    const int i0  = blockIdx.x * 8;
    const int b   = blockIdx.y;
    const int tid = threadIdx.x;
    const int lane = tid & 31;
    const int w   = tid >> 5;

    __shared__ float s_sp[8][SLP];

    for (int j = tid; j < 8 * SLP; j += 256)
        ((float*)s_sp)[j] = -3e38f;
    __syncthreads();

    const int i = i0 + w;
    const int r = b * SL + i;

    float4 h4[4];
#pragma unroll
    for (int k = 0; k < 4; k++)
        h4[k] = *(const float4*)(g_hd3 + (size_t)r * HT3 + lane * 4 + k * 128);

    for (int j = 0; j < i; j++) {
        const float* tr = g_hd3 + (size_t)(b * SL + j) * HT3 + 512;
        float s = 0.0f;
#pragma unroll
        for (int k = 0; k < 4; k++) {
            const float4 t4 = *(const float4*)(tr + lane * 4 + k * 128);
            s = fmaf(h4[k].x, t4.x, s);
            s = fmaf(h4[k].y, t4.y, s);
            s = fmaf(h4[k].z, t4.z, s);
            s = fmaf(h4[k].w, t4.w, s);
        }
#pragma unroll
        for (int o = 16; o > 0; o >>= 1) s += __shfl_xor_sync(0xffffffff, s, o);
        if (lane == 0 && g_rowmask[b * SL + j] > 0.5f) s_sp[w][j] = s;
    }

    // softmax of row w
    {
        float m = -3e38f;
        for (int j = lane; j < SL; j += 32) m = fmaxf(m, s_sp[w][j]);
#pragma unroll
        for (int o = 16; o > 0; o >>= 1) m = fmaxf(m, __shfl_xor_sync(0xffffffff, m, o));
        float sum = 0.0f;
        float ev[7];
#pragma unroll
        for (int q = 0; q < 7; q++) {
            const int j = lane + q * 32;
            float e = 0.0f;
            if (j < SL) {
                const float v = s_sp[w][j];
                if (v > -1e37f) e = expf(v - m);
            }
            ev[q] = e;
            sum += e;
        }
#pragma unroll
        for (int o = 16; o > 0; o >>= 1) sum += __shfl_xor_sync(0xffffffff, sum, o);
        const float inv = (sum > 0.0f) ? 1.0f / sum : 0.0f;
#pragma unroll
        for (int q = 0; q < 7; q++) {
            const int j = lane + q * 32;
            if (j < SL) s_sp[w][j] = ev[q] * inv;
        }
    }
    __syncthreads();

    // depend: 8 rows x 512 cols; thread handles cols 2*tid, 2*tid+1
    const int c2 = tid * 2;
    float2 acc[8];
#pragma unroll
    for (int ii = 0; ii < 8; ii++) acc[ii] = make_float2(0.0f, 0.0f);

    const int jmax = i0 + 7;
    for (int j = 0; j < jmax; j++) {
        const float2 hv = *(const float2*)(g_hidden + (size_t)(b * SL + j) * HDIM + c2);
#pragma unroll
        for (int ii = 0; ii < 8; ii++) {
            const float s = s_sp[ii][j];
            acc[ii].x = fmaf(s, hv.x, acc[ii].x);
            acc[ii].y = fmaf(s, hv.y, acc[ii].y);
        }
    }

#pragma unroll
    for (int ii = 0; ii < 8; ii++) {
        const size_t o = (size_t)(b * SL + i0 + ii) * HDIM + c2;
        *(float2*)(g_depend + o) = acc[ii];
        const __nv_bfloat16 hx = __float2bfloat16(acc[ii].x);
        const __nv_bfloat16 hy = __float2bfloat16(acc[ii].y);
        __nv_bfloat162 vh; vh.x = hx; vh.y = hy;
        __nv_bfloat162 vl;
        vl.x = __float2bfloat16(acc[ii].x - __bfloat162float(hx));
        vl.y = __float2bfloat16(acc[ii].y - __bfloat162float(hy));
        *(__nv_bfloat162*)(g_depHi + o) = vh;
        *(__nv_bfloat162*)(g_depLo + o) = vl;
    }
}

// ---------------- gate blend (reads gbuf slice of g_hd3, fused split output) -------
__global__ void enc_kernel() {
    const int idx = blockIdx.x * 256 + threadIdx.x;
    const int row = idx >> 9;
    const int col = idx & 511;
    const float gv = g_hd3[(size_t)row * HT3 + 1024 + col];
    const float g = 1.0f / (1.0f + expf(-gv));
    const float x = (g * g_hidden[idx] + (1.0f - g) * g_depend[idx]) * g_rowmask[row];
    g_enc[idx] = x;
    const __nv_bfloat16 h = __float2bfloat16(x);
    g_encHi[idx] = h;
    g_encLo[idx] = __float2bfloat16(x - __bfloat162float(h));
}

// ---------------- map2 + pool softmax ----------------
__global__ void pool_kernel(const float* __restrict__ wm2, const float* __restrict__ bm2) {
    const int b = blockIdx.x;
    const int tid = threadIdx.x;
    const int lane = tid & 31;
    const int warp = tid >> 5;

    __shared__ float sm2[SL];
    __shared__ float rbuf[256];

    for (int i = warp; i < SL; i += 8) {
        const float* mr = g_m1 + (size_t)(b * SL + i) * HDIM;
        float s = 0.0f;
        for (int k = lane; k < HDIM; k += 32) s = fmaf(mr[k], wm2[k], s);
#pragma unroll
        for (int o = 16; o > 0; o >>= 1) s += __shfl_xor_sync(0xffffffff, s, o);
        if (lane == 0) sm2[i] = s + bm2[0];
    }
    __syncthreads();

    const bool valid = (tid < SL) && (g_rowmask[b * SL + tid] > 0.5f);
    float v = valid ? sm2[tid] : -3e38f;
    rbuf[tid] = v;
    __syncthreads();
    for (int s = 128; s > 0; s >>= 1) {
        if (tid < s) rbuf[tid] = fmaxf(rbuf[tid], rbuf[tid + s]);
        __syncthreads();
    }
    const float m = rbuf[0];
    __syncthreads();
    float e = valid ? expf(sm2[tid] - m) : 0.0f;
    rbuf[tid] = e;
    __syncthreads();
    for (int s = 128; s > 0; s >>= 1) {
        if (tid < s) rbuf[tid] += rbuf[tid + s];
        __syncthreads();
    }
    const float ssum = rbuf[0];
    if (tid < SL) g_pool[b * SL + tid] = (ssum > 0.0f) ? e / ssum : 0.0f;
}

// A = (pool * enc) -> fp16 hi/lo (exact split)
__global__ void convA_kernel() {
    const int idx = blockIdx.x * 256 + threadIdx.x;
    const int row = idx >> 9;
    const float x = g_enc[idx] * g_pool[row];
    const __half h = __float2half_rn(x);
    g_Af16hi[idx] = h;
    g_Af16lo[idx] = __float2half_rn(x - __half2float(h));
}

// ---------------- launch ----------------
extern "C" void kernel_launch(void* const* d_in, const int* in_sizes, int n_in,
                              void* d_out, int out_size) {
    const int*   cas  = (const int*)d_in[0];
    const int*   tiiv = (const int*)d_in[1];
    const float* emb  = (const float*)d_in[2];
    const float* tl   = (const float*)d_in[3];
    const float* w1   = (const float*)d_in[4];
    const float* b1   = (const float*)d_in[5];
    const float* wh   = (const float*)d_in[6];
    const float* bh   = (const float*)d_in[7];
    const float* wt   = (const float*)d_in[8];
    const float* bt   = (const float*)d_in[9];
    const float* wg   = (const float*)d_in[10];
    const float* bg   = (const float*)d_in[11];
    const float* wm1  = (const float*)d_in[12];
    const float* bm1  = (const float*)d_in[13];
    const float* wti  = (const float*)d_in[14];
    const float* bti  = (const float*)d_in[15];
    const float* wm2  = (const float*)d_in[16];
    const float* bm2  = (const float*)d_in[17];
    const float* wout = (const float*)d_in[18];
    const float* bout = (const float*)d_in[19];
    float* out = (float*)d_out;

    float *hiddenP, *hd3P, *m1P, *rowmaskP, *tiP, *bias3P;
    int *tidxP;
    __nv_bfloat16 *casHiP, *casLoP, *tlHiP, *tlLoP, *hidHiP, *hidLoP, *depHiP, *depLoP;
    __nv_bfloat16 *encHiP, *encLoP, *wTHiP, *wTLoP;
    __half *Af16hiP, *Af16loP, *Bf16P;
    cudaGetSymbolAddress((void**)&hiddenP, g_hidden);
    cudaGetSymbolAddress((void**)&hd3P,    g_hd3);
    cudaGetSymbolAddress((void**)&m1P,     g_m1);
    cudaGetSymbolAddress((void**)&rowmaskP,g_rowmask);
    cudaGetSymbolAddress((void**)&tiP,     g_ti);
    cudaGetSymbolAddress((void**)&bias3P,  g_bias3);
    cudaGetSymbolAddress((void**)&tidxP,   g_tidx);
    cudaGetSymbolAddress((void**)&casHiP,  g_casHi);
    cudaGetSymbolAddress((void**)&casLoP,  g_casLo);
    cudaGetSymbolAddress((void**)&tlHiP,   g_tlHi);
    cudaGetSymbolAddress((void**)&tlLoP,   g_tlLo);
    cudaGetSymbolAddress((void**)&hidHiP,  g_hidHi);
    cudaGetSymbolAddress((void**)&hidLoP,  g_hidLo);
    cudaGetSymbolAddress((void**)&depHiP,  g_depHi);
    cudaGetSymbolAddress((void**)&depLoP,  g_depLo);
    cudaGetSymbolAddress((void**)&encHiP,  g_encHi);
    cudaGetSymbolAddress((void**)&encLoP,  g_encLo);
    cudaGetSymbolAddress((void**)&wTHiP,   g_wTHi);
    cudaGetSymbolAddress((void**)&wTLoP,   g_wTLo);
    cudaGetSymbolAddress((void**)&Af16hiP, g_Af16hi);
    cudaGetSymbolAddress((void**)&Af16loP, g_Af16lo);
    cudaGetSymbolAddress((void**)&Bf16P,   g_Bf16);

    cudaFuncSetAttribute(wout_gemm, cudaFuncAttributeMaxDynamicSharedMemorySize, WOUT_SMEM);

    prep_kernel<<<BBATCH, 256>>>(cas, tiiv);
    bias3_kernel<<<6, 256>>>(bh, bt, bg);

    // operand prep
    gatherSplit_kernel<<<(MROWS * HDIM) / 256, 256>>>(emb);
    split_kernel<<<(TDIM * HDIM + 255) / 256, 256>>>(tl, tlHiP, tlLoP, TDIM * HDIM);
    dim3 cT(16, 16), cB(32, 8);
    convT_kernel<<<cT, cB>>>(w1,  HDIM, wTHiP + 0 * WSLOT, wTLoP + 0 * WSLOT);
    convT_kernel<<<cT, cB>>>(wh,  HDIM, wTHiP + 1 * WSLOT, wTLoP + 1 * WSLOT);
    convT_kernel<<<cT, cB>>>(wt,  HDIM, wTHiP + 2 * WSLOT, wTLoP + 2 * WSLOT);
    convT_kernel<<<cT, cB>>>(wg,  HDIM, wTHiP + 3 * WSLOT, wTLoP + 3 * WSLOT);
    convT_kernel<<<cT, cB>>>(wg + (size_t)HDIM * HDIM, HDIM,
                             wTHiP + 4 * WSLOT, wTLoP + 4 * WSLOT);
    convT_kernel<<<cT, cB>>>(wm1, HDIM, wTHiP + 5 * WSLOT, wTLoP + 5 * WSLOT);
    convT_kernel<<<cT, cB>>>(wti, HDIM, wTHiP + 6 * WSLOT, wTLoP + 6 * WSLOT);
    convBf16_kernel<<<dim3(VDIM / 32, 16), cB>>>(wout);

    dim3 gH(HDIM / 128, MROWS / 128);     // (4, 50)
    dim3 gHT3(HT3 / 128, MROWS / 128);    // (12, 50)
    dim3 gV(VDIM / 128, MROWS / 128);     // (250, 50)

    // hidden = elu(cas_emb @ w1 + b1) * rowmask  (+ fused split)
    hmma_gemm<HEPI_ELU_MASK_SPLIT, false><<<gH, 256>>>(
        casHiP, casLoP, wTHiP + 0 * WSLOT, wTLoP + 0 * WSLOT,
        hiddenP, b1, nullptr, rowmaskP, hidHiP, hidLoP, nullptr, HDIM);

    // fused [head|tail|gbuf] = hidden @ [wh|wt|wg1]^T + bias3  (N=1536)
    hmma_gemm<HEPI_BIAS, false><<<gHT3, 256>>>(
        hidHiP, hidLoP, wTHiP + 1 * WSLOT, wTLoP + 1 * WSLOT,
        hd3P, bias3P, nullptr, nullptr, nullptr, nullptr, nullptr, HT3);

    // ti (101 distinct time rows, padded to 128): elu(tl @ wti + bti)
    hmma_gemm<HEPI_ELU, false><<<dim3(4, 1), 256>>>(
        tlHiP, tlLoP, wTHiP + 6 * WSLOT, wTLoP + 6 * WSLOT,
        tiP, bti, nullptr, nullptr, nullptr, nullptr, nullptr, HDIM);

    // attention -> depend (+ fused split), 8 rows/block
    attn_kernel<<<dim3(SL / 8, BBATCH), 256>>>();

    // gbuf += depend @ wg2^T   (into g_hd3 col slice 1024.., stride 1536)
    hmma_gemm<HEPI_ACC, false><<<gH, 256>>>(
        depHiP, depLoP, wTHiP + 4 * WSLOT, wTLoP + 4 * WSLOT,
        hd3P + 1024, nullptr, nullptr, nullptr, nullptr, nullptr, nullptr, HT3);

    // enc blend (+ fused split)
    enc_kernel<<<(MROWS * HDIM) / 256, 256>>>();

    // m1 = elu(enc@wm1 + bm1) * ti[tidx[row]]
    hmma_gemm<HEPI_ELU_TIMUL, false><<<gH, 256>>>(
        encHiP, encLoP, wTHiP + 5 * WSLOT, wTLoP + 5 * WSLOT,
        m1P, bm1, tidxP, nullptr, nullptr, nullptr, tiP, HDIM);

    // pool softmax over sequence
    pool_kernel<<<BBATCH, 256>>>(wm2, bm2);

    // A = pool*enc -> fp16 hi/lo
    convA_kernel<<<(MROWS * HDIM) / 256, 256>>>();

    // logits_out = A @ fp16(wout)^T + bout  (2-product split-fp16)
    wout_gemm<<<gV, 256, WOUT_SMEM>>>(Af16hiP, Af16loP, Bf16P, out, bout);
}

// round 17
// speedup vs baseline: 1.5258x; 1.0228x over previous
#include <cuda_runtime.h>
#include <cuda_bf16.h>
#include <cuda_fp16.h>
#include <math.h>
#include <stdint.h>

// Problem constants
#define BBATCH 32
#define SFULL  201
#define SL     200
#define HDIM   512
#define EDIM   512
#define VDIM   32000
#define TDIM   101
#define MROWS  (BBATCH * SL)   // 6400
#define HT3    1536            // head|tail|gate fused width

// ---------------- scratch (device globals; no allocation allowed) ----------------
__device__ float g_hidden[MROWS * HDIM];
__device__ float g_hd3   [MROWS * HT3];     // [head | tail | gbuf] fused
__device__ float g_m1    [MROWS * HDIM];
__device__ float g_depend[MROWS * HDIM];
__device__ float g_ti    [128 * HDIM];      // elu(tl@wti+bti), 101 rows (pad 128)
__device__ float g_bias3 [HT3];
__device__ float g_rowmask[MROWS];
__device__ float g_pool  [MROWS];
__device__ int   g_gidx  [MROWS];
__device__ int   g_tidx  [MROWS];

// split-bf16 operand buffers (H-dim stages)
__device__ __nv_bfloat16 g_casHi[MROWS * HDIM];
__device__ __nv_bfloat16 g_casLo[MROWS * HDIM];
__device__ __nv_bfloat16 g_tlHi[128 * HDIM];   // pad 101 -> 128 (zeros beyond)
__device__ __nv_bfloat16 g_tlLo[128 * HDIM];
__device__ __nv_bfloat16 g_hidHi[MROWS * HDIM];
__device__ __nv_bfloat16 g_hidLo[MROWS * HDIM];
__device__ __nv_bfloat16 g_depHi[MROWS * HDIM];
__device__ __nv_bfloat16 g_depLo[MROWS * HDIM];
__device__ __nv_bfloat16 g_encHi[MROWS * HDIM];
__device__ __nv_bfloat16 g_encLo[MROWS * HDIM];
// 7 transposed/split weights [512,512]: w1(0), wh(1), wt(2), wg1(3), wg2(4), wm1(5), wti(6)
// slots 1..3 contiguous -> fused [1536, 512] B for the triple GEMM
#define WSLOT (HDIM * HDIM)
__device__ __nv_bfloat16 g_wTHi[7 * WSLOT];
__device__ __nv_bfloat16 g_wTLo[7 * WSLOT];

// split-fp16 enc for the wout GEMM (pool folded into wout epilogue)
__device__ __half g_Af16hi[MROWS * HDIM];
__device__ __half g_Af16lo[MROWS * HDIM];
__device__ __half g_Bf16[(size_t)VDIM * HDIM];

// ---------------- base-PTX helpers (target is plain sm_103: no tcgen05!) --------
__device__ __forceinline__ uint32_t smem_u32(const void* p) {
    uint32_t a;
    asm("{ .reg .u64 t; cvta.to.shared.u64 t, %1; cvt.u32.u64 %0, t; }" : "=r"(a) : "l"(p));
    return a;
}

#define CP_ASYNC16(dst, src) \
    asm volatile("cp.async.cg.shared.global [%0], [%1], 16;" :: "r"(dst), "l"(src))
#define CP_COMMIT() asm volatile("cp.async.commit_group;" ::: "memory")
#define CP_WAIT1()  asm volatile("cp.async.wait_group 1;" ::: "memory")

#define LDSM4(r, addr)                                                        \
    asm volatile("ldmatrix.sync.aligned.m8n8.x4.shared.b16 {%0,%1,%2,%3}, [%4];" \
                 : "=r"((r)[0]), "=r"((r)[1]), "=r"((r)[2]), "=r"((r)[3])     \
                 : "r"(addr))

#define MMA_BF16(d, a, b0, b1)                                                \
    asm volatile("mma.sync.aligned.m16n8k16.row.col.f32.bf16.bf16.f32 "       \
                 "{%0,%1,%2,%3}, {%4,%5,%6,%7}, {%8,%9}, {%0,%1,%2,%3};"      \
                 : "+f"((d)[0]), "+f"((d)[1]), "+f"((d)[2]), "+f"((d)[3])     \
                 : "r"((a)[0]), "r"((a)[1]), "r"((a)[2]), "r"((a)[3]),        \
                   "r"(b0), "r"(b1))

#define MMA_F16(d, a, b0, b1)                                                 \
    asm volatile("mma.sync.aligned.m16n8k16.row.col.f32.f16.f16.f32 "         \
                 "{%0,%1,%2,%3}, {%4,%5,%6,%7}, {%8,%9}, {%0,%1,%2,%3};"      \
                 : "+f"((d)[0]), "+f"((d)[1]), "+f"((d)[2]), "+f"((d)[3])     \
                 : "r"((a)[0]), "r"((a)[1]), "r"((a)[2]), "r"((a)[3]),        \
                   "r"(b0), "r"(b1))

__device__ __forceinline__ float elu_f(float x) { return x > 0.0f ? x : expm1f(x); }

// ---------------- prep ----------------
__global__ void prep_kernel(const int* __restrict__ cas, const int* __restrict__ tii) {
    int b = blockIdx.x;
    int tid = threadIdx.x;
    __shared__ int red[256];
    int cnt = 0;
    for (int i = tid; i < SL; i += 256) cnt += (cas[b * SFULL + i] != 0);
    red[tid] = cnt;
    __syncthreads();
    for (int s = 128; s > 0; s >>= 1) {
        if (tid < s) red[tid] += red[tid + s];
        __syncthreads();
    }
    int len = red[0];
    for (int i = tid; i < SL; i += 256) {
        int r = b * SL + i;
        g_rowmask[r] = (i < len) ? 1.0f : 0.0f;
        g_gidx[r] = cas[b * SFULL + i];
        g_tidx[r] = tii[b * SFULL + i];
    }
}

__global__ void bias3_kernel(const float* __restrict__ bh, const float* __restrict__ bt,
                             const float* __restrict__ bg) {
    const int i = blockIdx.x * 256 + threadIdx.x;
    if (i >= HT3) return;
    g_bias3[i] = (i < 512) ? bh[i] : (i < 1024) ? bt[i - 512] : bg[i - 1024];
}

// ---------------- gather + split embedding rows ----------------
__global__ void gatherSplit_kernel(const float* __restrict__ emb) {
    const int idx = blockIdx.x * 256 + threadIdx.x;
    const int row = idx >> 9;
    const int col = idx & 511;
    const float x = emb[(size_t)g_gidx[row] * EDIM + col];
    const __nv_bfloat16 h = __float2bfloat16(x);
    g_casHi[idx] = h;
    g_casLo[idx] = __float2bfloat16(x - __bfloat162float(h));
}

__global__ void split_kernel(const float* __restrict__ src, __nv_bfloat16* __restrict__ hi,
                             __nv_bfloat16* __restrict__ lo, int n) {
    const int idx = blockIdx.x * 256 + threadIdx.x;
    if (idx >= n) return;
    const float x = src[idx];
    const __nv_bfloat16 h = __float2bfloat16(x);
    hi[idx] = h;
    lo[idx] = __float2bfloat16(x - __bfloat162float(h));
}

// ---------------- transpose + split (bf16) ----------------
__global__ void convT_kernel(const float* __restrict__ w, int ncols,
                             __nv_bfloat16* __restrict__ hi, __nv_bfloat16* __restrict__ lo) {
    __shared__ float t[32][33];
    const int nt = blockIdx.x * 32;
    const int kt = blockIdx.y * 32;
    const int tx = threadIdx.x;
    const int ty = threadIdx.y;
#pragma unroll
    for (int i = 0; i < 32; i += 8)
        t[ty + i][tx] = w[(size_t)(kt + ty + i) * ncols + nt + tx];
    __syncthreads();
#pragma unroll
    for (int i = 0; i < 32; i += 8) {
        const float x = t[tx][ty + i];
        const __nv_bfloat16 h = __float2bfloat16(x);
        const size_t o = (size_t)(nt + ty + i) * HDIM + kt + tx;
        hi[o] = h;
        lo[o] = __float2bfloat16(x - __bfloat162float(h));
    }
}

__global__ void convBf16_kernel(const float* __restrict__ w) {
    __shared__ float t[32][33];
    const int nt = blockIdx.x * 32;
    const int kt = blockIdx.y * 32;
    const int tx = threadIdx.x;
    const int ty = threadIdx.y;
#pragma unroll
    for (int i = 0; i < 32; i += 8)
        t[ty + i][tx] = w[(size_t)(kt + ty + i) * VDIM + nt + tx];
    __syncthreads();
#pragma unroll
    for (int i = 0; i < 32; i += 8)
        g_Bf16[(size_t)(nt + ty + i) * HDIM + kt + tx] = __float2half_rn(t[tx][ty + i]);
}

// ---------------- unified split-bf16 HMMA GEMM (128x128 tile) ----------------
#define STAGES 3
#define STAGE_ELEMS (128 * 32)

#define HEPI_BIAS           0
#define HEPI_ELU            1
#define HEPI_ELU_MASK_SPLIT 2
#define HEPI_ACC            3
#define HEPI_ELU_TIMUL      4   // C = elu(acc+bias) * aux[gidx[row]*512 + col]

template <int EPI, bool GATHER>
__global__ __launch_bounds__(256, 2)
void hmma_gemm(const __nv_bfloat16* __restrict__ Ahi, const __nv_bfloat16* __restrict__ Alo,
               const __nv_bfloat16* __restrict__ Bhi, const __nv_bfloat16* __restrict__ Blo,
               float* __restrict__ C, const float* __restrict__ bias,
               const int* __restrict__ gidx, const float* __restrict__ rowvec,
               __nv_bfloat16* __restrict__ Chi, __nv_bfloat16* __restrict__ Clo,
               const float* __restrict__ aux, int N) {
    __shared__ __align__(16) __nv_bfloat16 sA[STAGES * STAGE_ELEMS];
    __shared__ __align__(16) __nv_bfloat16 sB[STAGES * STAGE_ELEMS];

    const int tid  = threadIdx.x;
    const int lane = tid & 31;
    const int wid  = tid >> 5;
    const int wm   = wid >> 1;
    const int wn   = wid & 1;
    const int bn   = blockIdx.x * 128;
    const int bm   = blockIdx.y * 128;

    const uint32_t sAaddr = smem_u32(sA);
    const uint32_t sBaddr = smem_u32(sB);

    float acc[2][8][4];
#pragma unroll
    for (int t = 0; t < 2; t++)
#pragma unroll
        for (int n = 0; n < 8; n++)
#pragma unroll
            for (int q = 0; q < 4; q++) acc[t][n][q] = 0.0f;

    auto load_stage = [&](int stage, int kt) {
        const int kbase = kt * 16;
#pragma unroll
        for (int i = 0; i < 4; i++) {
            const int id   = tid + i * 256;
            const int isB  = id >> 9;
            const int sub  = id & 511;
            const int half = sub & 1;
            const int r    = (sub >> 1) & 127;
            const int hl   = (sub >> 8) & 1;
            const int c    = hl * 2 + half;
            const __nv_bfloat16* gsrc;
            if (isB) {
                gsrc = (hl ? Blo : Bhi) + (size_t)(bn + r) * HDIM + kbase + half * 8;
            } else {
                const int ar = GATHER ? gidx[bm + r] : (bm + r);
                gsrc = (hl ? Alo : Ahi) + (size_t)ar * HDIM + kbase + half * 8;
            }
            const uint32_t dst = (isB ? sBaddr : sAaddr) +
                (uint32_t)(stage * STAGE_ELEMS + r * 32 + (c ^ ((r >> 1) & 3)) * 8) * 2;
            CP_ASYNC16(dst, gsrc);
        }
    };

    load_stage(0, 0); CP_COMMIT();
    load_stage(1, 1); CP_COMMIT();

    const int a_m  = wm * 32 + (lane & 15);
    const int a_kg = lane >> 4;
    const int b_n  = wn * 64 + (lane & 7) + ((lane >> 4) & 1) * 8;
    const int b_kg = (lane >> 3) & 1;

    for (int kt = 0; kt < HDIM / 16; kt++) {
        const int s = kt % STAGES;
        CP_WAIT1();
        __syncthreads();

        if (kt + 2 < HDIM / 16) load_stage((kt + 2) % STAGES, kt + 2);
        CP_COMMIT();

        const uint32_t baseA = sAaddr + (uint32_t)(s * STAGE_ELEMS) * 2;
        const uint32_t baseB = sBaddr + (uint32_t)(s * STAGE_ELEMS) * 2;

        uint32_t aHi[2][4], aLo[2][4];
#pragma unroll
        for (int t = 0; t < 2; t++) {
            const int r = a_m + t * 16;
            const uint32_t sw = (uint32_t)((r >> 1) & 3);
            LDSM4(aHi[t], baseA + (uint32_t)(r * 32 + ((a_kg       ^ sw)) * 8) * 2);
            LDSM4(aLo[t], baseA + (uint32_t)(r * 32 + (((2 + a_kg) ^ sw)) * 8) * 2);
        }

#pragma unroll
        for (int np = 0; np < 4; np++) {
            const int n = b_n + np * 16;
            const uint32_t sw = (uint32_t)((n >> 1) & 3);
            uint32_t bHi[4], bLo[4];
            LDSM4(bHi, baseB + (uint32_t)(n * 32 + ((b_kg       ^ sw)) * 8) * 2);
            LDSM4(bLo, baseB + (uint32_t)(n * 32 + (((2 + b_kg) ^ sw)) * 8) * 2);
#pragma unroll
            for (int t = 0; t < 2; t++) {
                MMA_BF16(acc[t][2 * np],     aHi[t], bHi[0], bHi[1]);
                MMA_BF16(acc[t][2 * np + 1], aHi[t], bHi[2], bHi[3]);
                MMA_BF16(acc[t][2 * np],     aHi[t], bLo[0], bLo[1]);
                MMA_BF16(acc[t][2 * np + 1], aHi[t], bLo[2], bLo[3]);
                MMA_BF16(acc[t][2 * np],     aLo[t], bHi[0], bHi[1]);
                MMA_BF16(acc[t][2 * np + 1], aLo[t], bHi[2], bHi[3]);
            }
        }
    }

#pragma unroll
    for (int t = 0; t < 2; t++) {
        const int rbase = bm + wm * 32 + t * 16 + (lane >> 2);
#pragma unroll
        for (int ni = 0; ni < 8; ni++) {
            const int col = bn + wn * 64 + ni * 8 + (lane & 3) * 2;
            float bx = 0.0f, by = 0.0f;
            if (EPI != HEPI_ACC) { bx = bias[col]; by = bias[col + 1]; }
#pragma unroll
            for (int h = 0; h < 2; h++) {
                const int row = rbase + h * 8;
                float x = acc[t][ni][2 * h]     + bx;
                float y = acc[t][ni][2 * h + 1] + by;
                float* cp = C + (size_t)row * N + col;
                if (EPI == HEPI_BIAS) {
                    *(float2*)cp = make_float2(x, y);
                } else if (EPI == HEPI_ELU) {
                    *(float2*)cp = make_float2(elu_f(x), elu_f(y));
                } else if (EPI == HEPI_ELU_MASK_SPLIT) {
                    const float mk = rowvec[row];
                    x = elu_f(x) * mk; y = elu_f(y) * mk;
                    *(float2*)cp = make_float2(x, y);
                    const __nv_bfloat16 xh = __float2bfloat16(x);
                    const __nv_bfloat16 yh = __float2bfloat16(y);
                    __nv_bfloat162 vh; vh.x = xh; vh.y = yh;
                    __nv_bfloat162 vl;
                    vl.x = __float2bfloat16(x - __bfloat162float(xh));
                    vl.y = __float2bfloat16(y - __bfloat162float(yh));
                    *(__nv_bfloat162*)(Chi + (size_t)row * HDIM + col) = vh;
                    *(__nv_bfloat162*)(Clo + (size_t)row * HDIM + col) = vl;
                } else if (EPI == HEPI_ACC) {
                    float2 old = *(float2*)cp;
                    *(float2*)cp = make_float2(old.x + x, old.y + y);
                } else if (EPI == HEPI_ELU_TIMUL) {
                    const float* tr = aux + (size_t)gidx[row] * HDIM + col;
                    *(float2*)cp = make_float2(elu_f(x) * tr[0], elu_f(y) * tr[1]);
                }
            }
        }
    }
}

// ---------------- wout GEMM: 2-product split-fp16, k32 stages; pool in epilogue ---
// Epilogue structure identical to the proven R13 kernel; only delta is the
// per-row scale load inside the existing h loop (spill-safe).
#define WSTAGES 3
#define WA_SUB  (128 * 32)
#define WA_ST   (2 * WA_SUB)
#define WB_ST   (128 * 32)
#define WOUT_SMEM (WSTAGES * (WA_ST + WB_ST) * 2)

__global__ __launch_bounds__(256, 2)
void wout_gemm(const __half* __restrict__ Ahi, const __half* __restrict__ Alo,
               const __half* __restrict__ B,
               float* __restrict__ C, const float* __restrict__ bias,
               const float* __restrict__ rowscale) {
    extern __shared__ __align__(16) __half wsm[];
    __half* sA = wsm;
    __half* sB = wsm + WSTAGES * WA_ST;

    const int tid  = threadIdx.x;
    const int lane = tid & 31;
    const int wid  = tid >> 5;
    const int wm   = wid >> 1;
    const int wn   = wid & 1;
    const int bn   = blockIdx.x * 128;
    const int bm   = blockIdx.y * 128;

    const uint32_t sAaddr = smem_u32(sA);
    const uint32_t sBaddr = smem_u32(sB);

    float acc[2][8][4];
#pragma unroll
    for (int t = 0; t < 2; t++)
#pragma unroll
        for (int n = 0; n < 8; n++)
#pragma unroll
            for (int q = 0; q < 4; q++) acc[t][n][q] = 0.0f;

    auto load_stage = [&](int stage, int st) {
        const int kb = st * 32;
#pragma unroll
        for (int i = 0; i < 4; i++) {
            const int id   = tid + i * 256;
            const int s01  = id >> 9;
            const int sub  = id & 511;
            const int half = sub & 1;
            const int r    = (sub >> 1) & 127;
            const int hl   = (sub >> 8) & 1;
            const int c    = hl * 2 + half;
            const __half* gsrc = (hl ? Alo : Ahi) +
                (size_t)(bm + r) * HDIM + kb + s01 * 16 + half * 8;
            const uint32_t dst = sAaddr +
                (uint32_t)(stage * WA_ST + s01 * WA_SUB + r * 32 + (c ^ ((r >> 1) & 3)) * 8) * 2;
            CP_ASYNC16(dst, gsrc);
        }
#pragma unroll
        for (int i = 0; i < 2; i++) {
            const int id = tid + i * 256;
            const int qc = id & 3;
            const int r  = id >> 2;
            const __half* gsrc = B + (size_t)(bn + r) * HDIM + kb + qc * 8;
            const uint32_t dst = sBaddr +
                (uint32_t)(stage * WB_ST + r * 32 + (qc ^ ((r >> 1) & 3)) * 8) * 2;
            CP_ASYNC16(dst, gsrc);
        }
    };

    load_stage(0, 0); CP_COMMIT();
    load_stage(1, 1); CP_COMMIT();

    const int a_m  = wm * 32 + (lane & 15);
    const int a_kg = lane >> 4;
    const int b_n  = wn * 64 + (lane & 7) + ((lane >> 4) & 1) * 8;
    const int b_kg = (lane >> 3) & 1;

    for (int st = 0; st < HDIM / 32; st++) {
        const int s = st % WSTAGES;
        CP_WAIT1();
        __syncthreads();

        if (st + 2 < HDIM / 32) load_stage((st + 2) % WSTAGES, st + 2);
        CP_COMMIT();

        const uint32_t baseB = sBaddr + (uint32_t)(s * WB_ST) * 2;
#pragma unroll
        for (int hs = 0; hs < 2; hs++) {
            const uint32_t baseA = sAaddr + (uint32_t)(s * WA_ST + hs * WA_SUB) * 2;

            uint32_t aHi[2][4], aLo[2][4];
#pragma unroll
            for (int t = 0; t < 2; t++) {
                const int r = a_m + t * 16;
                const uint32_t sw = (uint32_t)((r >> 1) & 3);
                LDSM4(aHi[t], baseA + (uint32_t)(r * 32 + ((a_kg       ^ sw)) * 8) * 2);
                LDSM4(aLo[t], baseA + (uint32_t)(r * 32 + (((2 + a_kg) ^ sw)) * 8) * 2);
            }

#pragma unroll
            for (int np = 0; np < 4; np++) {
                const int n = b_n + np * 16;
                const uint32_t sw = (uint32_t)((n >> 1) & 3);
                uint32_t bF[4];
                LDSM4(bF, baseB + (uint32_t)(n * 32 + (((hs * 2 + b_kg) ^ sw)) * 8) * 2);
#pragma unroll
                for (int t = 0; t < 2; t++) {
                    MMA_F16(acc[t][2 * np],     aHi[t], bF[0], bF[1]);
                    MMA_F16(acc[t][2 * np + 1], aHi[t], bF[2], bF[3]);
                    MMA_F16(acc[t][2 * np],     aLo[t], bF[0], bF[1]);
                    MMA_F16(acc[t][2 * np + 1], aLo[t], bF[2], bF[3]);
                }
            }
        }
    }

#pragma unroll
    for (int t = 0; t < 2; t++) {
        const int rbase = bm + wm * 32 + t * 16 + (lane >> 2);
#pragma unroll
        for (int ni = 0; ni < 8; ni++) {
            const int col = bn + wn * 64 + ni * 8 + (lane & 3) * 2;
            const float bx = bias[col], by = bias[col + 1];
#pragma unroll
            for (int h = 0; h < 2; h++) {
                const int row = rbase + h * 8;
                const float p = rowscale[row];
                *(float2*)(C + (size_t)row * VDIM + col) =
                    make_float2(acc[t][ni][2 * h] * p + bx, acc[t][ni][2 * h + 1] * p + by);
            }
        }
    }
}

// ---------------- attention: 8 rows per block, 2x-unrolled loops ----------------
#define SLP 208
__global__ void attn_kernel() {
    const int i0  = blockIdx.x * 8;
    const int b   = blockIdx.y;
    const int tid = threadIdx.x;
    const int lane = tid & 31;
    const int w   = tid >> 5;

    __shared__ float s_sp[8][SLP];

    for (int j = tid; j < 8 * SLP; j += 256)
        ((float*)s_sp)[j] = -3e38f;
    __syncthreads();

    const int i = i0 + w;
    const int r = b * SL + i;

    float4 h4[4];
#pragma unroll
    for (int k = 0; k < 4; k++)
        h4[k] = *(const float4*)(g_hd3 + (size_t)r * HT3 + lane * 4 + k * 128);

    // logits: 2 j per iteration (independent chains)
    int j = 0;
    for (; j + 1 < i; j += 2) {
        const float* t0 = g_hd3 + (size_t)(b * SL + j) * HT3 + 512;
        const float* t1 = t0 + HT3;
        float s0 = 0.0f, s1 = 0.0f;
#pragma unroll
        for (int k = 0; k < 4; k++) {
            const float4 a4 = *(const float4*)(t0 + lane * 4 + k * 128);
            const float4 b4 = *(const float4*)(t1 + lane * 4 + k * 128);
            s0 = fmaf(h4[k].x, a4.x, s0); s1 = fmaf(h4[k].x, b4.x, s1);
            s0 = fmaf(h4[k].y, a4.y, s0); s1 = fmaf(h4[k].y, b4.y, s1);
            s0 = fmaf(h4[k].z, a4.z, s0); s1 = fmaf(h4[k].z, b4.z, s1);
            s0 = fmaf(h4[k].w, a4.w, s0); s1 = fmaf(h4[k].w, b4.w, s1);
        }
#pragma unroll
        for (int o = 16; o > 0; o >>= 1) {
            s0 += __shfl_xor_sync(0xffffffff, s0, o);
            s1 += __shfl_xor_sync(0xffffffff, s1, o);
        }
        if (lane == 0) {
            if (g_rowmask[b * SL + j] > 0.5f)     s_sp[w][j] = s0;
            if (g_rowmask[b * SL + j + 1] > 0.5f) s_sp[w][j + 1] = s1;
        }
    }
    if (j < i) {
        const float* t0 = g_hd3 + (size_t)(b * SL + j) * HT3 + 512;
        float s0 = 0.0f;
#pragma unroll
        for (int k = 0; k < 4; k++) {
            const float4 a4 = *(const float4*)(t0 + lane * 4 + k * 128);
            s0 = fmaf(h4[k].x, a4.x, s0);
            s0 = fmaf(h4[k].y, a4.y, s0);
            s0 = fmaf(h4[k].z, a4.z, s0);
            s0 = fmaf(h4[k].w, a4.w, s0);
        }
#pragma unroll
        for (int o = 16; o > 0; o >>= 1) s0 += __shfl_xor_sync(0xffffffff, s0, o);
        if (lane == 0 && g_rowmask[b * SL + j] > 0.5f) s_sp[w][j] = s0;
    }

    // softmax of row w
    {
        float m = -3e38f;
        for (int jj = lane; jj < SL; jj += 32) m = fmaxf(m, s_sp[w][jj]);
#pragma unroll
        for (int o = 16; o > 0; o >>= 1) m = fmaxf(m, __shfl_xor_sync(0xffffffff, m, o));
        float sum = 0.0f;
        float ev[7];
#pragma unroll
        for (int q = 0; q < 7; q++) {
            const int jj = lane + q * 32;
            float e = 0.0f;
            if (jj < SL) {
                const float v = s_sp[w][jj];
                if (v > -1e37f) e = expf(v - m);
            }
            ev[q] = e;
            sum += e;
        }
#pragma unroll
        for (int o = 16; o > 0; o >>= 1) sum += __shfl_xor_sync(0xffffffff, sum, o);
        const float inv = (sum > 0.0f) ? 1.0f / sum : 0.0f;
#pragma unroll
        for (int q = 0; q < 7; q++) {
            const int jj = lane + q * 32;
            if (jj < SL) s_sp[w][jj] = ev[q] * inv;
        }
    }
    __syncthreads();

    // depend: 2 j per iteration
    const int c2 = tid * 2;
    float2 acc[8];
#pragma unroll
    for (int ii = 0; ii < 8; ii++) acc[ii] = make_float2(0.0f, 0.0f);

    const int jmax = i0 + 7;
    int jj = 0;
    for (; jj + 1 < jmax; jj += 2) {
        const float2 hv0 = *(const float2*)(g_hidden + (size_t)(b * SL + jj) * HDIM + c2);
        const float2 hv1 = *(const float2*)(g_hidden + (size_t)(b * SL + jj + 1) * HDIM + c2);
#pragma unroll
        for (int ii = 0; ii < 8; ii++) {
            const float s0 = s_sp[ii][jj];
            const float s1 = s_sp[ii][jj + 1];
            acc[ii].x = fmaf(s0, hv0.x, fmaf(s1, hv1.x, acc[ii].x));
            acc[ii].y = fmaf(s0, hv0.y, fmaf(s1, hv1.y, acc[ii].y));
        }
    }
    if (jj < jmax) {
        const float2 hv0 = *(const float2*)(g_hidden + (size_t)(b * SL + jj) * HDIM + c2);
#pragma unroll
        for (int ii = 0; ii < 8; ii++) {
            const float s0 = s_sp[ii][jj];
            acc[ii].x = fmaf(s0, hv0.x, acc[ii].x);
            acc[ii].y = fmaf(s0, hv0.y, acc[ii].y);
        }
    }

#pragma unroll
    for (int ii = 0; ii < 8; ii++) {
        const size_t o = (size_t)(b * SL + i0 + ii) * HDIM + c2;
        *(float2*)(g_depend + o) = acc[ii];
        const __nv_bfloat16 hx = __float2bfloat16(acc[ii].x);
        const __nv_bfloat16 hy = __float2bfloat16(acc[ii].y);
        __nv_bfloat162 vh; vh.x = hx; vh.y = hy;
        __nv_bfloat162 vl;
        vl.x = __float2bfloat16(acc[ii].x - __bfloat162float(hx));
        vl.y = __float2bfloat16(acc[ii].y - __bfloat162float(hy));
        *(__nv_bfloat162*)(g_depHi + o) = vh;
        *(__nv_bfloat162*)(g_depLo + o) = vl;
    }
}

// ---------------- gate blend: emits bf16 split (m1 GEMM) + fp16 split (wout) -------
__global__ void enc_kernel() {
    const int idx = blockIdx.x * 256 + threadIdx.x;
    const int row = idx >> 9;
    const int col = idx & 511;
    const float gv = g_hd3[(size_t)row * HT3 + 1024 + col];
    const float g = 1.0f / (1.0f + expf(-gv));
    const float x = (g * g_hidden[idx] + (1.0f - g) * g_depend[idx]) * g_rowmask[row];
    const __nv_bfloat16 h = __float2bfloat16(x);
    g_encHi[idx] = h;
    g_encLo[idx] = __float2bfloat16(x - __bfloat162float(h));
    const __half hf = __float2half_rn(x);
    g_Af16hi[idx] = hf;
    g_Af16lo[idx] = __float2half_rn(x - __half2float(hf));
}

// ---------------- map2 + pool softmax ----------------
__global__ void pool_kernel(const float* __restrict__ wm2, const float* __restrict__ bm2) {
    const int b = blockIdx.x;
    const int tid = threadIdx.x;
    const int lane = tid & 31;
    const int warp = tid >> 5;

    __shared__ float sm2[SL];
    __shared__ float rbuf[256];

    for (int i = warp; i < SL; i += 8) {
        const float* mr = g_m1 + (size_t)(b * SL + i) * HDIM;
        float s = 0.0f;
        for (int k = lane; k < HDIM; k += 32) s = fmaf(mr[k], wm2[k], s);
#pragma unroll
        for (int o = 16; o > 0; o >>= 1) s += __shfl_xor_sync(0xffffffff, s, o);
        if (lane == 0) sm2[i] = s + bm2[0];
    }
    __syncthreads();

    const bool valid = (tid < SL) && (g_rowmask[b * SL + tid] > 0.5f);
    float v = valid ? sm2[tid] : -3e38f;
    rbuf[tid] = v;
    __syncthreads();
    for (int s = 128; s > 0; s >>= 1) {
        if (tid < s) rbuf[tid] = fmaxf(rbuf[tid], rbuf[tid + s]);
        __syncthreads();
    }
    const float m = rbuf[0];
    __syncthreads();
    float e = valid ? expf(sm2[tid] - m) : 0.0f;
    rbuf[tid] = e;
    __syncthreads();
    for (int s = 128; s > 0; s >>= 1) {
        if (tid < s) rbuf[tid] += rbuf[tid + s];
        __syncthreads();
    }
    const float ssum = rbuf[0];
    if (tid < SL) g_pool[b * SL + tid] = (ssum > 0.0f) ? e / ssum : 0.0f;
}

// ---------------- launch ----------------
extern "C" void kernel_launch(void* const* d_in, const int* in_sizes, int n_in,
                              void* d_out, int out_size) {
    const int*   cas  = (const int*)d_in[0];
    const int*   tiiv = (const int*)d_in[1];
    const float* emb  = (const float*)d_in[2];
    const float* tl   = (const float*)d_in[3];
    const float* w1   = (const float*)d_in[4];
    const float* b1   = (const float*)d_in[5];
    const float* wh   = (const float*)d_in[6];
    const float* bh   = (const float*)d_in[7];
    const float* wt   = (const float*)d_in[8];
    const float* bt   = (const float*)d_in[9];
    const float* wg   = (const float*)d_in[10];
    const float* bg   = (const float*)d_in[11];
    const float* wm1  = (const float*)d_in[12];
    const float* bm1  = (const float*)d_in[13];
    const float* wti  = (const float*)d_in[14];
    const float* bti  = (const float*)d_in[15];
    const float* wm2  = (const float*)d_in[16];
    const float* bm2  = (const float*)d_in[17];
    const float* wout = (const float*)d_in[18];
    const float* bout = (const float*)d_in[19];
    float* out = (float*)d_out;

    float *hiddenP, *hd3P, *m1P, *rowmaskP, *tiP, *bias3P, *poolP;
    int *tidxP;
    __nv_bfloat16 *casHiP, *casLoP, *tlHiP, *tlLoP, *hidHiP, *hidLoP, *depHiP, *depLoP;
    __nv_bfloat16 *encHiP, *encLoP, *wTHiP, *wTLoP;
    __half *Af16hiP, *Af16loP, *Bf16P;
    cudaGetSymbolAddress((void**)&hiddenP, g_hidden);
    cudaGetSymbolAddress((void**)&hd3P,    g_hd3);
    cudaGetSymbolAddress((void**)&m1P,     g_m1);
    cudaGetSymbolAddress((void**)&rowmaskP,g_rowmask);
    cudaGetSymbolAddress((void**)&tiP,     g_ti);
    cudaGetSymbolAddress((void**)&bias3P,  g_bias3);
    cudaGetSymbolAddress((void**)&poolP,   g_pool);
    cudaGetSymbolAddress((void**)&tidxP,   g_tidx);
    cudaGetSymbolAddress((void**)&casHiP,  g_casHi);
    cudaGetSymbolAddress((void**)&casLoP,  g_casLo);
    cudaGetSymbolAddress((void**)&tlHiP,   g_tlHi);
    cudaGetSymbolAddress((void**)&tlLoP,   g_tlLo);
    cudaGetSymbolAddress((void**)&hidHiP,  g_hidHi);
    cudaGetSymbolAddress((void**)&hidLoP,  g_hidLo);
    cudaGetSymbolAddress((void**)&depHiP,  g_depHi);
    cudaGetSymbolAddress((void**)&depLoP,  g_depLo);
    cudaGetSymbolAddress((void**)&encHiP,  g_encHi);
    cudaGetSymbolAddress((void**)&encLoP,  g_encLo);
    cudaGetSymbolAddress((void**)&wTHiP,   g_wTHi);
    cudaGetSymbolAddress((void**)&wTLoP,   g_wTLo);
    cudaGetSymbolAddress((void**)&Af16hiP, g_Af16hi);
    cudaGetSymbolAddress((void**)&Af16loP, g_Af16lo);
    cudaGetSymbolAddress((void**)&Bf16P,   g_Bf16);

    cudaFuncSetAttribute(wout_gemm, cudaFuncAttributeMaxDynamicSharedMemorySize, WOUT_SMEM);

    prep_kernel<<<BBATCH, 256>>>(cas, tiiv);
    bias3_kernel<<<6, 256>>>(bh, bt, bg);

    // operand prep
    gatherSplit_kernel<<<(MROWS * HDIM) / 256, 256>>>(emb);
    split_kernel<<<(TDIM * HDIM + 255) / 256, 256>>>(tl, tlHiP, tlLoP, TDIM * HDIM);
    dim3 cT(16, 16), cB(32, 8);
    convT_kernel<<<cT, cB>>>(w1,  HDIM, wTHiP + 0 * WSLOT, wTLoP + 0 * WSLOT);
    convT_kernel<<<cT, cB>>>(wh,  HDIM, wTHiP + 1 * WSLOT, wTLoP + 1 * WSLOT);
    convT_kernel<<<cT, cB>>>(wt,  HDIM, wTHiP + 2 * WSLOT, wTLoP + 2 * WSLOT);
    convT_kernel<<<cT, cB>>>(wg,  HDIM, wTHiP + 3 * WSLOT, wTLoP + 3 * WSLOT);
    convT_kernel<<<cT, cB>>>(wg + (size_t)HDIM * HDIM, HDIM,
                             wTHiP + 4 * WSLOT, wTLoP + 4 * WSLOT);
    convT_kernel<<<cT, cB>>>(wm1, HDIM, wTHiP + 5 * WSLOT, wTLoP + 5 * WSLOT);
    convT_kernel<<<cT, cB>>>(wti, HDIM, wTHiP + 6 * WSLOT, wTLoP + 6 * WSLOT);
    convBf16_kernel<<<dim3(VDIM / 32, 16), cB>>>(wout);

    dim3 gH(HDIM / 128, MROWS / 128);     // (4, 50)
    dim3 gHT3(HT3 / 128, MROWS / 128);    // (12, 50)
    dim3 gV(VDIM / 128, MROWS / 128);     // (250, 50)

    // hidden = elu(cas_emb @ w1 + b1) * rowmask  (+ fused split)
    hmma_gemm<HEPI_ELU_MASK_SPLIT, false><<<gH, 256>>>(
        casHiP, casLoP, wTHiP + 0 * WSLOT, wTLoP + 0 * WSLOT,
        hiddenP, b1, nullptr, rowmaskP, hidHiP, hidLoP, nullptr, HDIM);

    // fused [head|tail|gbuf] = hidden @ [wh|wt|wg1]^T + bias3  (N=1536)
    hmma_gemm<HEPI_BIAS, false><<<gHT3, 256>>>(
        hidHiP, hidLoP, wTHiP + 1 * WSLOT, wTLoP + 1 * WSLOT,
        hd3P, bias3P, nullptr, nullptr, nullptr, nullptr, nullptr, HT3);

    // ti (101 distinct time rows, padded to 128): elu(tl @ wti + bti)
    hmma_gemm<HEPI_ELU, false><<<dim3(4, 1), 256>>>(
        tlHiP, tlLoP, wTHiP + 6 * WSLOT, wTLoP + 6 * WSLOT,
        tiP, bti, nullptr, nullptr, nullptr, nullptr, nullptr, HDIM);

    // attention -> depend (+ fused split), 8 rows/block
    attn_kernel<<<dim3(SL / 8, BBATCH), 256>>>();

    // gbuf += depend @ wg2^T   (into g_hd3 col slice 1024.., stride 1536)
    hmma_gemm<HEPI_ACC, false><<<gH, 256>>>(
        depHiP, depLoP, wTHiP + 4 * WSLOT, wTLoP + 4 * WSLOT,
        hd3P + 1024, nullptr, nullptr, nullptr, nullptr, nullptr, nullptr, HT3);

    // enc blend (+ fused bf16 AND fp16 splits)
    enc_kernel<<<(MROWS * HDIM) / 256, 256>>>();

    // m1 = elu(enc@wm1 + bm1) * ti[tidx[row]]
    hmma_gemm<HEPI_ELU_TIMUL, false><<<gH, 256>>>(
        encHiP, encLoP, wTHiP + 5 * WSLOT, wTLoP + 5 * WSLOT,
        m1P, bm1, tidxP, nullptr, nullptr, nullptr, tiP, HDIM);

    // pool softmax over sequence
    pool_kernel<<<BBATCH, 256>>>(wm2, bm2);

    // logits_out = pool ⊙ (enc @ fp16(wout)^T) + bout
    wout_gemm<<<gV, 256, WOUT_SMEM>>>(Af16hiP, Af16loP, Bf16P, out, bout, poolP);
}